// round 6
// baseline (speedup 1.0000x reference)
#include <cuda_runtime.h>
#include <cuda_bf16.h>
#include <cstdint>

// ---------------------------------------------------------------------------
// Problem constants
#define BDIM   64
#define NDIM   32
#define DDIM   512
#define NPAIR  992                 // 32*31 ordered pairs
#define MROWS  (BDIM * NPAIR)      // 63488 output rows
#define BNROWS (BDIM * NDIM)       // 2048 person rows

// Scratch (device globals; no allocations allowed)
__device__ float g_P[(size_t)BNROWS * 1024];                      // 8 MB fp32 partials
__device__ __align__(16) unsigned short g_Fh[BNROWS * 512];       // bf16 hi of F
__device__ __align__(16) unsigned short g_Fl[BNROWS * 512];
__device__ __align__(16) unsigned short g_W1h[1024 * 512];        // W1 rearranged [c][k]
__device__ __align__(16) unsigned short g_W1l[1024 * 512];
__device__ __align__(16) unsigned short g_W2h[512 * 512];
__device__ __align__(16) unsigned short g_W2l[512 * 512];

// ---------------------------------------------------------------------------
// Helpers
// ---------------------------------------------------------------------------
__device__ __forceinline__ uint32_t smem_u32(const void* p) {
    uint32_t a;
    asm("{ .reg .u64 t; cvta.to.shared.u64 t, %1; cvt.u32.u64 %0, t; }"
        : "=r"(a) : "l"(p));
    return a;
}
__device__ __forceinline__ void ldsm_x4(uint32_t* r, uint32_t addr) {
    asm volatile("ldmatrix.sync.aligned.m8n8.x4.shared.b16 {%0,%1,%2,%3},[%4];"
        : "=r"(r[0]), "=r"(r[1]), "=r"(r[2]), "=r"(r[3]) : "r"(addr));
}
__device__ __forceinline__ void ldsm_x2(uint32_t* r, uint32_t addr) {
    asm volatile("ldmatrix.sync.aligned.m8n8.x2.shared.b16 {%0,%1},[%2];"
        : "=r"(r[0]), "=r"(r[1]) : "r"(addr));
}
__device__ __forceinline__ void mma_bf16(float* d, const uint32_t* a, const uint32_t* b) {
    asm volatile(
        "mma.sync.aligned.m16n8k16.row.col.f32.bf16.bf16.f32 "
        "{%0,%1,%2,%3},{%4,%5,%6,%7},{%8,%9},{%0,%1,%2,%3};"
        : "+f"(d[0]), "+f"(d[1]), "+f"(d[2]), "+f"(d[3])
        : "r"(a[0]), "r"(a[1]), "r"(a[2]), "r"(a[3]), "r"(b[0]), "r"(b[1]));
}
__device__ __forceinline__ void cp_async16(uint32_t dst, const void* src) {
    asm volatile("cp.async.cg.shared.global [%0], [%1], 16;"
        :: "r"(dst), "l"(__cvta_generic_to_global(src)) : "memory");
}
#define CP_COMMIT() asm volatile("cp.async.commit_group;" ::: "memory")
#define CP_WAIT(n)  asm volatile("cp.async.wait_group %0;" :: "n"(n) : "memory")

// bf16 hi/lo split of two floats -> two packed bf16x2 words
__device__ __forceinline__ void split2(float x0, float x1, uint32_t& h, uint32_t& l) {
    __nv_bfloat16 h0 = __float2bfloat16(x0);
    __nv_bfloat16 h1 = __float2bfloat16(x1);
    h = (uint32_t)__bfloat16_as_ushort(h0) | ((uint32_t)__bfloat16_as_ushort(h1) << 16);
    __nv_bfloat16 l0 = __float2bfloat16(x0 - __bfloat162float(h0));
    __nv_bfloat16 l1 = __float2bfloat16(x1 - __bfloat162float(h1));
    l = (uint32_t)__bfloat16_as_ushort(l0) | ((uint32_t)__bfloat16_as_ushort(l1) << 16);
}

// ---------------------------------------------------------------------------
// Input split kernels
// ---------------------------------------------------------------------------
__global__ __launch_bounds__(256)
void k_w2split(const float* __restrict__ W2)
{
    int idx = blockIdx.x * 256 + threadIdx.x;         // 65536 float4s
    float4 v = reinterpret_cast<const float4*>(W2)[idx];
    uint32_t h0, l0, h1, l1;
    split2(v.x, v.y, h0, l0);
    split2(v.z, v.w, h1, l1);
    reinterpret_cast<uint2*>(g_W2h)[idx] = make_uint2(h0, h1);
    reinterpret_cast<uint2*>(g_W2l)[idx] = make_uint2(l0, l1);
}

__global__ __launch_bounds__(256)
void k_fsplit(const float* __restrict__ F)
{
    int idx = blockIdx.x * 256 + threadIdx.x;         // 262144 float4s
    float4 v = reinterpret_cast<const float4*>(F)[idx];
    uint32_t h0, l0, h1, l1;
    split2(v.x, v.y, h0, l0);
    split2(v.z, v.w, h1, l1);
    reinterpret_cast<uint2*>(g_Fh)[idx] = make_uint2(h0, h1);
    reinterpret_cast<uint2*>(g_Fl)[idx] = make_uint2(l0, l1);
}

// W1' [c][k] = W1[c&511][(c>>9)*512 + k],  c<1024, k<512
__global__ __launch_bounds__(256)
void k_w1split(const float* __restrict__ W1)
{
    int idx = blockIdx.x * 256 + threadIdx.x;         // 131072 float4s
    int L = idx * 4;
    int c = L >> 9;
    int k = L & 511;
    const float4 v = *reinterpret_cast<const float4*>(
        W1 + (size_t)(c & 511) * 1024 + ((c >> 9) << 9) + k);
    uint32_t h0, l0, h1, l1;
    split2(v.x, v.y, h0, l0);
    split2(v.z, v.w, h1, l1);
    reinterpret_cast<uint2*>(g_W1h)[idx] = make_uint2(h0, h1);
    reinterpret_cast<uint2*>(g_W1l)[idx] = make_uint2(l0, l1);
}

// ---------------------------------------------------------------------------
// GEMM A: P = F @ W1'^T (+ b1 on first 512 cols). M=2048, N=1024, K=512.
// 3-stage cp.async 128x128 kernel from R4 (measured 23us, tensor ~50%).
// ---------------------------------------------------------------------------
#define STG      65536
#define SMEM_A3  (3 * STG + 1024)

__global__ __launch_bounds__(256, 1)
void k_gemmA(const unsigned short* __restrict__ Ah_g,
             const unsigned short* __restrict__ Al_g,
             const unsigned short* __restrict__ Bh_g,
             const unsigned short* __restrict__ Bl_g,
             const float* __restrict__ bias,
             float* __restrict__ out)
{
    extern __shared__ char dsm[];
    const int tid = threadIdx.x;
    const int wid = tid >> 5;
    const int lid = tid & 31;

    uint32_t raw = smem_u32(dsm);
    const uint32_t dbase = (raw + 1023u) & ~1023u;

    const int rowBase = blockIdx.y * 128;
    const int colBase = blockIdx.x * 128;

    const unsigned short* Asrc_h = Ah_g + (size_t)rowBase * 512;
    const unsigned short* Asrc_l = Al_g + (size_t)rowBase * 512;
    const unsigned short* Bsrc_h = Bh_g + (size_t)colBase * 512;
    const unsigned short* Bsrc_l = Bl_g + (size_t)colBase * 512;

    auto ldt = [&](uint32_t dst, const unsigned short* src, int c) {
#pragma unroll
        for (int g = 0; g < 4; ++g) {
            const int q = tid + 256 * g;
            const int row = q >> 3;
            const int kb  = q & 7;
            const uint32_t off = (uint32_t)row * 128 + (uint32_t)((kb ^ (row & 7)) << 4);
            cp_async16(dst + off, src + (size_t)row * 512 + c * 64 + kb * 8);
        }
    };
    auto loadStage = [&](int c, int s) {
        const uint32_t st = dbase + s * STG;
        ldt(st,         Asrc_h, c);
        ldt(st + 16384, Asrc_l, c);
        ldt(st + 32768, Bsrc_h, c);
        ldt(st + 49152, Bsrc_l, c);
    };

    const int wm = (wid & 3) * 32;
    const int wn = (wid >> 2) * 64;

    float acc[2][8][4];
#pragma unroll
    for (int mi = 0; mi < 2; ++mi)
#pragma unroll
        for (int ni = 0; ni < 8; ++ni)
#pragma unroll
            for (int q = 0; q < 4; ++q) acc[mi][ni][q] = 0.0f;

    auto compute = [&](int s) {
        const uint32_t AhB = dbase + s * STG;
        const uint32_t BhB = AhB + 32768;
        const int mrow = lid & 15;
        const int ksel = lid >> 4;
        const int bn_  = lid & 7;
        const int bsel = (lid >> 3) & 1;
#pragma unroll
        for (int ks = 0; ks < 4; ++ks) {
            uint32_t ah[2][4], al[2][4], bh[8][2], bl[8][2];
#pragma unroll
            for (int mi = 0; mi < 2; ++mi) {
                const uint32_t r = (uint32_t)(wm + mi * 16 + mrow);
                const uint32_t kb = (uint32_t)(ks * 2 + ksel);
                const uint32_t addr = AhB + r * 128 + ((kb ^ (r & 7)) << 4);
                ldsm_x4(ah[mi], addr);
                ldsm_x4(al[mi], addr + 16384);
            }
#pragma unroll
            for (int ni = 0; ni < 8; ++ni) {
                const uint32_t n = (uint32_t)(wn + ni * 8 + bn_);
                const uint32_t kb = (uint32_t)(ks * 2 + bsel);
                const uint32_t addr = BhB + n * 128 + ((kb ^ (n & 7)) << 4);
                ldsm_x2(bh[ni], addr);
                ldsm_x2(bl[ni], addr + 16384);
            }
#pragma unroll
            for (int mi = 0; mi < 2; ++mi)
#pragma unroll
                for (int ni = 0; ni < 8; ++ni) {
                    mma_bf16(acc[mi][ni], ah[mi], bh[ni]);
                    mma_bf16(acc[mi][ni], ah[mi], bl[ni]);
                    mma_bf16(acc[mi][ni], al[mi], bh[ni]);
                }
        }
    };

    loadStage(0, 0); CP_COMMIT();
    loadStage(1, 1); CP_COMMIT();

    for (int c = 0; c < 8; ++c) {
        CP_WAIT(1);
        __syncthreads();
        if (c + 2 < 8) loadStage(c + 2, (c + 2) % 3);
        CP_COMMIT();
        compute(c % 3);
    }

    // epilogue: bias only on first 512 columns (P1 half)
    {
        const int t2 = (lid & 3) * 2;
        const int gg = lid >> 2;
        float2 bb[8];
#pragma unroll
        for (int ni = 0; ni < 8; ++ni) {
            if (colBase < 512)
                bb[ni] = *reinterpret_cast<const float2*>(bias + colBase + wn + ni * 8 + t2);
            else
                bb[ni] = make_float2(0.f, 0.f);
        }
#pragma unroll
        for (int mi = 0; mi < 2; ++mi) {
            const int r0 = rowBase + wm + mi * 16 + gg;
#pragma unroll
            for (int ni = 0; ni < 8; ++ni) {
                const int cc = colBase + wn + ni * 8 + t2;
                float2 v0, v1;
                v0.x = acc[mi][ni][0] + bb[ni].x;
                v0.y = acc[mi][ni][1] + bb[ni].y;
                v1.x = acc[mi][ni][2] + bb[ni].x;
                v1.y = acc[mi][ni][3] + bb[ni].y;
                *reinterpret_cast<float2*>(out + (size_t)r0 * 1024 + cc) = v0;
                *reinterpret_cast<float2*>(out + (size_t)(r0 + 8) * 1024 + cc) = v1;
            }
        }
    }
}

// ---------------------------------------------------------------------------
// GEMM B (warp-specialized, fused H production):
//   out[r, n] = relu(P1[b,i,:] + P2[b,j,:]) @ W2^T + b2
// 320 threads: warps 0-7 = MMA consumers (4Mx2N grid of 32x64 warp tiles),
// warps 8-9 = producers (A: read P from L2, relu+split+STS; B: cp.async W2).
// 2-stage lock-step pipeline via __syncthreads. K = 8 chunks of 64.
// Stage 64KB: Ah 16K | Al 16K | Bh 16K | Bl 16K.
// ---------------------------------------------------------------------------
#define SMEM_B2  (2 * STG + 1024)

__global__ __launch_bounds__(320, 1)
void k_gemmB(const float* __restrict__ b2, float* __restrict__ out)
{
    extern __shared__ char dsm[];
    __shared__ int s_rowI[128], s_rowJ[128];

    const int tid = threadIdx.x;
    const int wid = tid >> 5;
    const int lid = tid & 31;

    uint32_t raw = smem_u32(dsm);
    const uint32_t dbase = (raw + 1023u) & ~1023u;
    char* dptr = dsm + (dbase - raw);

    const int rowBase = blockIdx.y * 128;
    const int colBase = blockIdx.x * 128;

    if (tid < 128) {
        int r = rowBase + tid;
        int b = r / NPAIR;
        int p = r - b * NPAIR;
        int i = p / 31;
        int jj = p - i * 31;
        int j = jj + (jj >= i ? 1 : 0);
        s_rowI[tid] = (b * NDIM + i) * 1024;
        s_rowJ[tid] = (b * NDIM + j) * 1024 + 512;
    }
    __syncthreads();

    // ---------------- producers: warps 8-9 (ptid 0..63) ----------------
    const int ptid = tid - 256;

    auto produceA = [&](int c, int s) {
        char* Ah = dptr + s * STG;
        char* Al = Ah + 16384;
#pragma unroll
        for (int rr = 0; rr < 2; ++rr) {
            const int row = ptid + rr * 64;
            const float* p1 = g_P + s_rowI[row] + c * 64;
            const float* p2 = g_P + s_rowJ[row] + c * 64;
            const uint32_t rs = (uint32_t)(row & 7);
            const uint32_t ro = (uint32_t)row * 128;
#pragma unroll
            for (int kb = 0; kb < 8; ++kb) {
                float4 u0 = *reinterpret_cast<const float4*>(p1 + kb * 8);
                float4 u1 = *reinterpret_cast<const float4*>(p1 + kb * 8 + 4);
                float4 v0 = *reinterpret_cast<const float4*>(p2 + kb * 8);
                float4 v1 = *reinterpret_cast<const float4*>(p2 + kb * 8 + 4);
                float x0 = fmaxf(u0.x + v0.x, 0.f), x1 = fmaxf(u0.y + v0.y, 0.f);
                float x2 = fmaxf(u0.z + v0.z, 0.f), x3 = fmaxf(u0.w + v0.w, 0.f);
                float x4 = fmaxf(u1.x + v1.x, 0.f), x5 = fmaxf(u1.y + v1.y, 0.f);
                float x6 = fmaxf(u1.z + v1.z, 0.f), x7 = fmaxf(u1.w + v1.w, 0.f);
                uint4 H, L;
                split2(x0, x1, H.x, L.x);
                split2(x2, x3, H.y, L.y);
                split2(x4, x5, H.z, L.z);
                split2(x6, x7, H.w, L.w);
                const uint32_t off = ro + (((uint32_t)kb ^ rs) << 4);
                *reinterpret_cast<uint4*>(Ah + off) = H;
                *reinterpret_cast<uint4*>(Al + off) = L;
            }
        }
    };

    auto loadB = [&](int c, int s) {
        const uint32_t Bh = dbase + s * STG + 32768;
#pragma unroll
        for (int g = 0; g < 16; ++g) {
            const int q = ptid + 64 * g;          // 1024 chunks
            const int row = q >> 3;
            const int kb  = q & 7;
            const uint32_t off = (uint32_t)row * 128 + (uint32_t)((kb ^ (row & 7)) << 4);
            const size_t so = (size_t)(colBase + row) * 512 + c * 64 + kb * 8;
            cp_async16(Bh + off,         g_W2h + so);
            cp_async16(Bh + 16384 + off, g_W2l + so);
        }
        CP_COMMIT();
    };

    // ---------------- consumers: warps 0-7 ----------------
    const int wm = (wid & 3) * 32;
    const int wn = (wid >> 2) * 64;

    float acc[2][8][4];
#pragma unroll
    for (int mi = 0; mi < 2; ++mi)
#pragma unroll
        for (int ni = 0; ni < 8; ++ni)
#pragma unroll
            for (int q = 0; q < 4; ++q) acc[mi][ni][q] = 0.0f;

    auto compute = [&](int s) {
        const uint32_t AhB = dbase + s * STG;
        const uint32_t BhB = AhB + 32768;
        const int mrow = lid & 15;
        const int ksel = lid >> 4;
        const int bn2   = lid & 7;
        const int khalf = (lid >> 3) & 1;
        const int tsel  = (lid >> 4) & 1;
#pragma unroll
        for (int ks = 0; ks < 4; ++ks) {
            uint32_t ah[2][4], al[2][4], bh[8][2], bl[8][2];
#pragma unroll
            for (int mi = 0; mi < 2; ++mi) {
                const uint32_t r = (uint32_t)(wm + mi * 16 + mrow);
                const uint32_t kb = (uint32_t)(ks * 2 + ksel);
                const uint32_t addr = AhB + r * 128 + ((kb ^ (r & 7)) << 4);
                ldsm_x4(ah[mi], addr);
                ldsm_x4(al[mi], addr + 16384);
            }
            // B: ldmatrix x4 loads tile pairs (2 n-tiles x 2 k-halves)
#pragma unroll
            for (int nip = 0; nip < 4; ++nip) {
                const uint32_t n = (uint32_t)(wn + (nip * 2 + tsel) * 8 + bn2);
                const uint32_t kb = (uint32_t)(ks * 2 + khalf);
                const uint32_t addr = BhB + n * 128 + ((kb ^ (n & 7)) << 4);
                uint32_t t[4];
                ldsm_x4(t, addr);
                bh[2 * nip][0] = t[0]; bh[2 * nip][1] = t[1];
                bh[2 * nip + 1][0] = t[2]; bh[2 * nip + 1][1] = t[3];
                ldsm_x4(t, addr + 16384);
                bl[2 * nip][0] = t[0]; bl[2 * nip][1] = t[1];
                bl[2 * nip + 1][0] = t[2]; bl[2 * nip + 1][1] = t[3];
            }
#pragma unroll
            for (int mi = 0; mi < 2; ++mi)
#pragma unroll
                for (int ni = 0; ni < 8; ++ni) {
                    mma_bf16(acc[mi][ni], ah[mi], bh[ni]);
                    mma_bf16(acc[mi][ni], ah[mi], bl[ni]);
                    mma_bf16(acc[mi][ni], al[mi], bh[ni]);
                }
        }
    };

    // ---------------- pipeline ----------------
    if (wid >= 8) {
        produceA(0, 0);
        loadB(0, 0);
        CP_WAIT(0);
    }
    __syncthreads();

    for (int c = 0; c < 8; ++c) {
        const int s = c & 1;
        if (wid >= 8) {
            if (c + 1 < 8) {
                produceA(c + 1, s ^ 1);
                loadB(c + 1, s ^ 1);
                CP_WAIT(0);
            }
        } else {
            compute(s);
        }
        __syncthreads();
    }

    // ---------------- epilogue (MMA warps only) ----------------
    if (wid < 8) {
        const int t2 = (lid & 3) * 2;
        const int gg = lid >> 2;
        float2 bb[8];
#pragma unroll
        for (int ni = 0; ni < 8; ++ni)
            bb[ni] = *reinterpret_cast<const float2*>(b2 + colBase + wn + ni * 8 + t2);

#pragma unroll
        for (int mi = 0; mi < 2; ++mi) {
            const int r0 = rowBase + wm + mi * 16 + gg;
#pragma unroll
            for (int ni = 0; ni < 8; ++ni) {
                const int cc = colBase + wn + ni * 8 + t2;
                float2 v0, v1;
                v0.x = acc[mi][ni][0] + bb[ni].x;
                v0.y = acc[mi][ni][1] + bb[ni].y;
                v1.x = acc[mi][ni][2] + bb[ni].x;
                v1.y = acc[mi][ni][3] + bb[ni].y;
                *reinterpret_cast<float2*>(out + (size_t)r0 * 512 + cc) = v0;
                *reinterpret_cast<float2*>(out + (size_t)(r0 + 8) * 512 + cc) = v1;
            }
        }
    }
}

// ---------------------------------------------------------------------------
extern "C" void kernel_launch(void* const* d_in, const int* in_sizes, int n_in,
                              void* d_out, int out_size)
{
    const float* F  = (const float*)d_in[0];   // person_feats (64,32,512)
    const float* W1 = (const float*)d_in[1];   // (512, 1024)
    const float* b1 = (const float*)d_in[2];   // (512,)
    const float* W2 = (const float*)d_in[3];   // (512, 512)
    const float* b2 = (const float*)d_in[4];   // (512,)
    float* out = (float*)d_out;                // (64, 992, 512)

    cudaFuncSetAttribute(k_gemmA, cudaFuncAttributeMaxDynamicSharedMemorySize, SMEM_A3);
    cudaFuncSetAttribute(k_gemmB, cudaFuncAttributeMaxDynamicSharedMemorySize, SMEM_B2);

    unsigned short *Fh, *Fl, *W1h, *W1l;
    float* P;
    cudaGetSymbolAddress((void**)&Fh,  g_Fh);
    cudaGetSymbolAddress((void**)&Fl,  g_Fl);
    cudaGetSymbolAddress((void**)&W1h, g_W1h);
    cudaGetSymbolAddress((void**)&W1l, g_W1l);
    cudaGetSymbolAddress((void**)&P,   g_P);

    // 1) split inputs to bf16 hi/lo
    k_w2split<<<256, 256>>>(W2);
    k_fsplit<<<1024, 256>>>(F);
    k_w1split<<<512, 256>>>(W1);

    // 2) P = F @ W1'^T (+ b1 on first 512 cols): M=2048, N=1024
    {
        dim3 g(8, 16);
        k_gemmA<<<g, 256, SMEM_A3>>>(Fh, Fl, W1h, W1l, b1, P);
    }

    // 3) out = relu(P1+P2) @ W2^T + b2: M=63488, N=512 (fused producer)
    {
        dim3 g(4, MROWS / 128);
        k_gemmB<<<g, 320, SMEM_B2>>>(b2, out);
    }
}

// round 7
// speedup vs baseline: 2.4952x; 2.4952x over previous
#include <cuda_runtime.h>
#include <cuda_bf16.h>
#include <cuda_fp16.h>
#include <cstdint>

// ---------------------------------------------------------------------------
// Problem constants
#define BDIM   64
#define NDIM   32
#define DDIM   512
#define NPAIR  992                 // 32*31 ordered pairs
#define MROWS  (BDIM * NPAIR)      // 63488 output rows
#define BNROWS (BDIM * NDIM)       // 2048 person rows

// Scratch (device globals; no allocations allowed)
__device__ float g_P[(size_t)BNROWS * 1024];                      // 8 MB fp32 partials
__device__ __align__(16) unsigned short g_Fh[BNROWS * 512];       // bf16 hi of F
__device__ __align__(16) unsigned short g_Fl[BNROWS * 512];
__device__ __align__(16) unsigned short g_W1h[1024 * 512];        // W1 rearranged [c][k]
__device__ __align__(16) unsigned short g_W1l[1024 * 512];
__device__ __align__(16) unsigned short g_W2h[512 * 512];         // fp16 of W2
__device__ __align__(16) unsigned short g_Hh[(size_t)MROWS * 512]; // fp16 hi of H
__device__ __align__(16) unsigned short g_Hl[(size_t)MROWS * 512]; // fp16 lo of H

// ---------------------------------------------------------------------------
// Helpers
// ---------------------------------------------------------------------------
__device__ __forceinline__ uint32_t smem_u32(const void* p) {
    uint32_t a;
    asm("{ .reg .u64 t; cvta.to.shared.u64 t, %1; cvt.u32.u64 %0, t; }"
        : "=r"(a) : "l"(p));
    return a;
}
__device__ __forceinline__ void ldsm_x4(uint32_t* r, uint32_t addr) {
    asm volatile("ldmatrix.sync.aligned.m8n8.x4.shared.b16 {%0,%1,%2,%3},[%4];"
        : "=r"(r[0]), "=r"(r[1]), "=r"(r[2]), "=r"(r[3]) : "r"(addr));
}
__device__ __forceinline__ void ldsm_x2(uint32_t* r, uint32_t addr) {
    asm volatile("ldmatrix.sync.aligned.m8n8.x2.shared.b16 {%0,%1},[%2];"
        : "=r"(r[0]), "=r"(r[1]) : "r"(addr));
}
__device__ __forceinline__ void mma_bf16(float* d, const uint32_t* a, const uint32_t* b) {
    asm volatile(
        "mma.sync.aligned.m16n8k16.row.col.f32.bf16.bf16.f32 "
        "{%0,%1,%2,%3},{%4,%5,%6,%7},{%8,%9},{%0,%1,%2,%3};"
        : "+f"(d[0]), "+f"(d[1]), "+f"(d[2]), "+f"(d[3])
        : "r"(a[0]), "r"(a[1]), "r"(a[2]), "r"(a[3]), "r"(b[0]), "r"(b[1]));
}
__device__ __forceinline__ void mma_f16(float* d, const uint32_t* a, const uint32_t* b) {
    asm volatile(
        "mma.sync.aligned.m16n8k16.row.col.f32.f16.f16.f32 "
        "{%0,%1,%2,%3},{%4,%5,%6,%7},{%8,%9},{%0,%1,%2,%3};"
        : "+f"(d[0]), "+f"(d[1]), "+f"(d[2]), "+f"(d[3])
        : "r"(a[0]), "r"(a[1]), "r"(a[2]), "r"(a[3]), "r"(b[0]), "r"(b[1]));
}
__device__ __forceinline__ void cp_async16(uint32_t dst, const void* src) {
    asm volatile("cp.async.cg.shared.global [%0], [%1], 16;"
        :: "r"(dst), "l"(__cvta_generic_to_global(src)) : "memory");
}
#define CP_COMMIT() asm volatile("cp.async.commit_group;" ::: "memory")
#define CP_WAIT(n)  asm volatile("cp.async.wait_group %0;" :: "n"(n) : "memory")

// bf16 hi/lo split of two floats -> two packed bf16x2 words
__device__ __forceinline__ void split2(float x0, float x1, uint32_t& h, uint32_t& l) {
    __nv_bfloat16 h0 = __float2bfloat16(x0);
    __nv_bfloat16 h1 = __float2bfloat16(x1);
    h = (uint32_t)__bfloat16_as_ushort(h0) | ((uint32_t)__bfloat16_as_ushort(h1) << 16);
    __nv_bfloat16 l0 = __float2bfloat16(x0 - __bfloat162float(h0));
    __nv_bfloat16 l1 = __float2bfloat16(x1 - __bfloat162float(h1));
    l = (uint32_t)__bfloat16_as_ushort(l0) | ((uint32_t)__bfloat16_as_ushort(l1) << 16);
}

// fp16 hi/lo split of two floats -> two packed f16x2 words (~22-bit total)
__device__ __forceinline__ void split2h(float x0, float x1, uint32_t& h, uint32_t& l) {
    __half h0 = __float2half(x0);
    __half h1 = __float2half(x1);
    h = (uint32_t)__half_as_ushort(h0) | ((uint32_t)__half_as_ushort(h1) << 16);
    __half l0 = __float2half(x0 - __half2float(h0));
    __half l1 = __float2half(x1 - __half2float(h1));
    l = (uint32_t)__half_as_ushort(l0) | ((uint32_t)__half_as_ushort(l1) << 16);
}

// ---------------------------------------------------------------------------
// Input split kernels
// ---------------------------------------------------------------------------
__global__ __launch_bounds__(256)
void k_w2half(const float* __restrict__ W2)
{
    int idx = blockIdx.x * 256 + threadIdx.x;         // 65536 float4s
    float4 v = reinterpret_cast<const float4*>(W2)[idx];
    __half2 a = __floats2half2_rn(v.x, v.y);
    __half2 b = __floats2half2_rn(v.z, v.w);
    reinterpret_cast<uint2*>(g_W2h)[idx] =
        make_uint2(*reinterpret_cast<uint32_t*>(&a), *reinterpret_cast<uint32_t*>(&b));
}

__global__ __launch_bounds__(256)
void k_fsplit(const float* __restrict__ F)
{
    int idx = blockIdx.x * 256 + threadIdx.x;         // 262144 float4s
    float4 v = reinterpret_cast<const float4*>(F)[idx];
    uint32_t h0, l0, h1, l1;
    split2(v.x, v.y, h0, l0);
    split2(v.z, v.w, h1, l1);
    reinterpret_cast<uint2*>(g_Fh)[idx] = make_uint2(h0, h1);
    reinterpret_cast<uint2*>(g_Fl)[idx] = make_uint2(l0, l1);
}

// W1' [c][k] = W1[c&511][(c>>9)*512 + k],  c<1024, k<512
__global__ __launch_bounds__(256)
void k_w1split(const float* __restrict__ W1)
{
    int idx = blockIdx.x * 256 + threadIdx.x;         // 131072 float4s
    int L = idx * 4;
    int c = L >> 9;
    int k = L & 511;
    const float4 v = *reinterpret_cast<const float4*>(
        W1 + (size_t)(c & 511) * 1024 + ((c >> 9) << 9) + k);
    uint32_t h0, l0, h1, l1;
    split2(v.x, v.y, h0, l0);
    split2(v.z, v.w, h1, l1);
    reinterpret_cast<uint2*>(g_W1h)[idx] = make_uint2(h0, h1);
    reinterpret_cast<uint2*>(g_W1l)[idx] = make_uint2(l0, l1);
}

// ---------------------------------------------------------------------------
// H split: H[r][k] = relu(P[b*32+i][k] + P[b*32+j][512+k]) -> fp16 hi/lo
// 8 warps per block, one row per warp, 16 elems per lane.
// ---------------------------------------------------------------------------
__global__ __launch_bounds__(256)
void k_hsplit()
{
    const int r   = blockIdx.x * 8 + (threadIdx.x >> 5);
    const int lid = threadIdx.x & 31;
    const int b = r / NPAIR;
    const int p = r - b * NPAIR;
    const int i = p / 31;
    const int jj = p - i * 31;
    const int j = jj + (jj >= i ? 1 : 0);

    const float* p1 = g_P + (size_t)(b * NDIM + i) * 1024 + lid * 16;
    const float* p2 = g_P + (size_t)(b * NDIM + j) * 1024 + 512 + lid * 16;
    unsigned short* hh = g_Hh + (size_t)r * 512 + lid * 16;
    unsigned short* hl = g_Hl + (size_t)r * 512 + lid * 16;

#pragma unroll
    for (int g = 0; g < 2; ++g) {                     // 2 groups of 8 elems
        float4 a0 = *reinterpret_cast<const float4*>(p1 + g * 8);
        float4 a1 = *reinterpret_cast<const float4*>(p1 + g * 8 + 4);
        float4 c0 = *reinterpret_cast<const float4*>(p2 + g * 8);
        float4 c1 = *reinterpret_cast<const float4*>(p2 + g * 8 + 4);
        float x0 = fmaxf(a0.x + c0.x, 0.f), x1 = fmaxf(a0.y + c0.y, 0.f);
        float x2 = fmaxf(a0.z + c0.z, 0.f), x3 = fmaxf(a0.w + c0.w, 0.f);
        float x4 = fmaxf(a1.x + c1.x, 0.f), x5 = fmaxf(a1.y + c1.y, 0.f);
        float x6 = fmaxf(a1.z + c1.z, 0.f), x7 = fmaxf(a1.w + c1.w, 0.f);
        uint4 H, L;
        split2h(x0, x1, H.x, L.x);
        split2h(x2, x3, H.y, L.y);
        split2h(x4, x5, H.z, L.z);
        split2h(x6, x7, H.w, L.w);
        *reinterpret_cast<uint4*>(hh + g * 8) = H;
        *reinterpret_cast<uint4*>(hl + g * 8) = L;
    }
}

// ---------------------------------------------------------------------------
// GEMM A: P = F @ W1'^T (+ b1 on first 512 cols). M=2048, N=1024, K=512.
// 3-term split-bf16, 3-stage cp.async (R4-measured: 23us, tensor ~50%).
// ---------------------------------------------------------------------------
#define STG_A    65536
#define SMEM_A3  (3 * STG_A + 1024)

__global__ __launch_bounds__(256, 1)
void k_gemmA(const unsigned short* __restrict__ Ah_g,
             const unsigned short* __restrict__ Al_g,
             const unsigned short* __restrict__ Bh_g,
             const unsigned short* __restrict__ Bl_g,
             const float* __restrict__ bias,
             float* __restrict__ out)
{
    extern __shared__ char dsm[];
    const int tid = threadIdx.x;
    const int wid = tid >> 5;
    const int lid = tid & 31;

    uint32_t raw = smem_u32(dsm);
    const uint32_t dbase = (raw + 1023u) & ~1023u;

    const int rowBase = blockIdx.y * 128;
    const int colBase = blockIdx.x * 128;

    const unsigned short* Asrc_h = Ah_g + (size_t)rowBase * 512;
    const unsigned short* Asrc_l = Al_g + (size_t)rowBase * 512;
    const unsigned short* Bsrc_h = Bh_g + (size_t)colBase * 512;
    const unsigned short* Bsrc_l = Bl_g + (size_t)colBase * 512;

    auto ldt = [&](uint32_t dst, const unsigned short* src, int c) {
#pragma unroll
        for (int g = 0; g < 4; ++g) {
            const int q = tid + 256 * g;
            const int row = q >> 3;
            const int kb  = q & 7;
            const uint32_t off = (uint32_t)row * 128 + (uint32_t)((kb ^ (row & 7)) << 4);
            cp_async16(dst + off, src + (size_t)row * 512 + c * 64 + kb * 8);
        }
    };
    auto loadStage = [&](int c, int s) {
        const uint32_t st = dbase + s * STG_A;
        ldt(st,         Asrc_h, c);
        ldt(st + 16384, Asrc_l, c);
        ldt(st + 32768, Bsrc_h, c);
        ldt(st + 49152, Bsrc_l, c);
    };

    const int wm = (wid & 3) * 32;
    const int wn = (wid >> 2) * 64;

    float acc[2][8][4];
#pragma unroll
    for (int mi = 0; mi < 2; ++mi)
#pragma unroll
        for (int ni = 0; ni < 8; ++ni)
#pragma unroll
            for (int q = 0; q < 4; ++q) acc[mi][ni][q] = 0.0f;

    auto compute = [&](int s) {
        const uint32_t AhB = dbase + s * STG_A;
        const uint32_t BhB = AhB + 32768;
        const int mrow = lid & 15;
        const int ksel = lid >> 4;
        const int bn_  = lid & 7;
        const int bsel = (lid >> 3) & 1;
#pragma unroll
        for (int ks = 0; ks < 4; ++ks) {
            uint32_t ah[2][4], al[2][4], bh[8][2], bl[8][2];
#pragma unroll
            for (int mi = 0; mi < 2; ++mi) {
                const uint32_t r = (uint32_t)(wm + mi * 16 + mrow);
                const uint32_t kb = (uint32_t)(ks * 2 + ksel);
                const uint32_t addr = AhB + r * 128 + ((kb ^ (r & 7)) << 4);
                ldsm_x4(ah[mi], addr);
                ldsm_x4(al[mi], addr + 16384);
            }
#pragma unroll
            for (int ni = 0; ni < 8; ++ni) {
                const uint32_t n = (uint32_t)(wn + ni * 8 + bn_);
                const uint32_t kb = (uint32_t)(ks * 2 + bsel);
                const uint32_t addr = BhB + n * 128 + ((kb ^ (n & 7)) << 4);
                ldsm_x2(bh[ni], addr);
                ldsm_x2(bl[ni], addr + 16384);
            }
#pragma unroll
            for (int mi = 0; mi < 2; ++mi)
#pragma unroll
                for (int ni = 0; ni < 8; ++ni) {
                    mma_bf16(acc[mi][ni], ah[mi], bh[ni]);
                    mma_bf16(acc[mi][ni], ah[mi], bl[ni]);
                    mma_bf16(acc[mi][ni], al[mi], bh[ni]);
                }
        }
    };

    loadStage(0, 0); CP_COMMIT();
    loadStage(1, 1); CP_COMMIT();

    for (int c = 0; c < 8; ++c) {
        CP_WAIT(1);
        __syncthreads();
        if (c + 2 < 8) loadStage(c + 2, (c + 2) % 3);
        CP_COMMIT();
        compute(c % 3);
    }

    // epilogue: bias only on first 512 columns (P1 half)
    {
        const int t2 = (lid & 3) * 2;
        const int gg = lid >> 2;
        float2 bb[8];
#pragma unroll
        for (int ni = 0; ni < 8; ++ni) {
            if (colBase < 512)
                bb[ni] = *reinterpret_cast<const float2*>(bias + colBase + wn + ni * 8 + t2);
            else
                bb[ni] = make_float2(0.f, 0.f);
        }
#pragma unroll
        for (int mi = 0; mi < 2; ++mi) {
            const int r0 = rowBase + wm + mi * 16 + gg;
#pragma unroll
            for (int ni = 0; ni < 8; ++ni) {
                const int cc = colBase + wn + ni * 8 + t2;
                float2 v0, v1;
                v0.x = acc[mi][ni][0] + bb[ni].x;
                v0.y = acc[mi][ni][1] + bb[ni].y;
                v1.x = acc[mi][ni][2] + bb[ni].x;
                v1.y = acc[mi][ni][3] + bb[ni].y;
                *reinterpret_cast<float2*>(out + (size_t)r0 * 1024 + cc) = v0;
                *reinterpret_cast<float2*>(out + (size_t)(r0 + 8) * 1024 + cc) = v1;
            }
        }
    }
}

// ---------------------------------------------------------------------------
// GEMM B: out = (Hh + Hl) @ W2h^T + b2   (fp16 2-term, fp32 accumulate)
// M=63488, N=512, K=512. CTA 128x128, 8 warps 4x2, K in 8 chunks of 64.
// 3-stage cp.async; stage 48KB: Ah 16K | Al 16K | Bh 16K.
// ---------------------------------------------------------------------------
#define STG_B    49152
#define SMEM_B3  (3 * STG_B + 1024)

__global__ __launch_bounds__(256, 1)
void k_gemmB(const float* __restrict__ b2, float* __restrict__ out)
{
    extern __shared__ char dsm[];
    const int tid = threadIdx.x;
    const int wid = tid >> 5;
    const int lid = tid & 31;

    uint32_t raw = smem_u32(dsm);
    const uint32_t dbase = (raw + 1023u) & ~1023u;

    const int rowBase = blockIdx.y * 128;
    const int colBase = blockIdx.x * 128;

    const unsigned short* Asrc_h = g_Hh + (size_t)rowBase * 512;
    const unsigned short* Asrc_l = g_Hl + (size_t)rowBase * 512;
    const unsigned short* Bsrc_h = g_W2h + (size_t)colBase * 512;

    auto ldt = [&](uint32_t dst, const unsigned short* src, int c) {
#pragma unroll
        for (int g = 0; g < 4; ++g) {
            const int q = tid + 256 * g;
            const int row = q >> 3;
            const int kb  = q & 7;
            const uint32_t off = (uint32_t)row * 128 + (uint32_t)((kb ^ (row & 7)) << 4);
            cp_async16(dst + off, src + (size_t)row * 512 + c * 64 + kb * 8);
        }
    };
    auto loadStage = [&](int c, int s) {
        const uint32_t st = dbase + s * STG_B;
        ldt(st,         Asrc_h, c);
        ldt(st + 16384, Asrc_l, c);
        ldt(st + 32768, Bsrc_h, c);
    };

    const int wm = (wid & 3) * 32;
    const int wn = (wid >> 2) * 64;

    float acc[2][8][4];
#pragma unroll
    for (int mi = 0; mi < 2; ++mi)
#pragma unroll
        for (int ni = 0; ni < 8; ++ni)
#pragma unroll
            for (int q = 0; q < 4; ++q) acc[mi][ni][q] = 0.0f;

    auto compute = [&](int s) {
        const uint32_t AhB = dbase + s * STG_B;
        const uint32_t BhB = AhB + 32768;
        const int mrow  = lid & 15;
        const int ksel  = lid >> 4;
        const int bn2   = lid & 7;
        const int khalf = (lid >> 3) & 1;
        const int tsel  = (lid >> 4) & 1;
#pragma unroll
        for (int ks = 0; ks < 4; ++ks) {
            uint32_t ah[2][4], al[2][4], bh[8][2];
#pragma unroll
            for (int mi = 0; mi < 2; ++mi) {
                const uint32_t r = (uint32_t)(wm + mi * 16 + mrow);
                const uint32_t kb = (uint32_t)(ks * 2 + ksel);
                const uint32_t addr = AhB + r * 128 + ((kb ^ (r & 7)) << 4);
                ldsm_x4(ah[mi], addr);
                ldsm_x4(al[mi], addr + 16384);
            }
            // B: each ldmatrix x4 grabs 2 n-tiles x 2 k-halves
#pragma unroll
            for (int nip = 0; nip < 4; ++nip) {
                const uint32_t n = (uint32_t)(wn + (nip * 2 + tsel) * 8 + bn2);
                const uint32_t kb = (uint32_t)(ks * 2 + khalf);
                const uint32_t addr = BhB + n * 128 + ((kb ^ (n & 7)) << 4);
                uint32_t t[4];
                ldsm_x4(t, addr);
                bh[2 * nip][0] = t[0]; bh[2 * nip][1] = t[1];
                bh[2 * nip + 1][0] = t[2]; bh[2 * nip + 1][1] = t[3];
            }
#pragma unroll
            for (int mi = 0; mi < 2; ++mi)
#pragma unroll
                for (int ni = 0; ni < 8; ++ni) {
                    mma_f16(acc[mi][ni], ah[mi], bh[ni]);
                    mma_f16(acc[mi][ni], al[mi], bh[ni]);
                }
        }
    };

    loadStage(0, 0); CP_COMMIT();
    loadStage(1, 1); CP_COMMIT();

    for (int c = 0; c < 8; ++c) {
        CP_WAIT(1);
        __syncthreads();
        if (c + 2 < 8) loadStage(c + 2, (c + 2) % 3);
        CP_COMMIT();
        compute(c % 3);
    }

    // epilogue
    {
        const int t2 = (lid & 3) * 2;
        const int gg = lid >> 2;
        float2 bb[8];
#pragma unroll
        for (int ni = 0; ni < 8; ++ni)
            bb[ni] = *reinterpret_cast<const float2*>(b2 + colBase + wn + ni * 8 + t2);

#pragma unroll
        for (int mi = 0; mi < 2; ++mi) {
            const int r0 = rowBase + wm + mi * 16 + gg;
#pragma unroll
            for (int ni = 0; ni < 8; ++ni) {
                const int cc = colBase + wn + ni * 8 + t2;
                float2 v0, v1;
                v0.x = acc[mi][ni][0] + bb[ni].x;
                v0.y = acc[mi][ni][1] + bb[ni].y;
                v1.x = acc[mi][ni][2] + bb[ni].x;
                v1.y = acc[mi][ni][3] + bb[ni].y;
                *reinterpret_cast<float2*>(out + (size_t)r0 * 512 + cc) = v0;
                *reinterpret_cast<float2*>(out + (size_t)(r0 + 8) * 512 + cc) = v1;
            }
        }
    }
}

// ---------------------------------------------------------------------------
extern "C" void kernel_launch(void* const* d_in, const int* in_sizes, int n_in,
                              void* d_out, int out_size)
{
    const float* F  = (const float*)d_in[0];   // person_feats (64,32,512)
    const float* W1 = (const float*)d_in[1];   // (512, 1024)
    const float* b1 = (const float*)d_in[2];   // (512,)
    const float* W2 = (const float*)d_in[3];   // (512, 512)
    const float* b2 = (const float*)d_in[4];   // (512,)
    float* out = (float*)d_out;                // (64, 992, 512)

    cudaFuncSetAttribute(k_gemmA, cudaFuncAttributeMaxDynamicSharedMemorySize, SMEM_A3);
    cudaFuncSetAttribute(k_gemmB, cudaFuncAttributeMaxDynamicSharedMemorySize, SMEM_B3);

    unsigned short *Fh, *Fl, *W1h, *W1l;
    float* P;
    cudaGetSymbolAddress((void**)&Fh,  g_Fh);
    cudaGetSymbolAddress((void**)&Fl,  g_Fl);
    cudaGetSymbolAddress((void**)&W1h, g_W1h);
    cudaGetSymbolAddress((void**)&W1l, g_W1l);
    cudaGetSymbolAddress((void**)&P,   g_P);

    // 1) split inputs (W2 -> fp16; F/W1 -> bf16 hi/lo)
    k_w2half<<<256, 256>>>(W2);
    k_fsplit<<<1024, 256>>>(F);
    k_w1split<<<512, 256>>>(W1);

    // 2) P = F @ W1'^T (+ b1 on first 512 cols): M=2048, N=1024
    {
        dim3 g(8, 16);
        k_gemmA<<<g, 256, SMEM_A3>>>(Fh, Fl, W1h, W1l, b1, P);
    }

    // 3) H = fp16-split(relu(P1 + P2))
    k_hsplit<<<MROWS / 8, 256>>>();

    // 4) out = (Hh+Hl) @ W2h^T + b2: M=63488, N=512
    {
        dim3 g(4, MROWS / 128);
        k_gemmB<<<g, 256, SMEM_B3>>>(b2, out);
    }
}

// round 9
// speedup vs baseline: 4.1197x; 1.6510x over previous
#include <cuda_runtime.h>
#include <cuda_bf16.h>
#include <cuda_fp16.h>
#include <cstdint>

// ---------------------------------------------------------------------------
// Problem constants
#define BDIM   64
#define NDIM   32
#define DDIM   512
#define NPAIR  992                 // 32*31 ordered pairs
#define MROWS  (BDIM * NPAIR)      // 63488 output rows
#define BNROWS (BDIM * NDIM)       // 2048 person rows

// Scratch (device globals; no allocations allowed)
__device__ float g_P[(size_t)BNROWS * 1024];                      // 8 MB fp32 partials
__device__ __align__(16) unsigned short g_Fh[BNROWS * 512];       // bf16 hi of F
__device__ __align__(16) unsigned short g_Fl[BNROWS * 512];
__device__ __align__(16) unsigned short g_W1h[1024 * 512];        // W1 rearranged [c][k]
__device__ __align__(16) unsigned short g_W1l[1024 * 512];
__device__ __align__(16) unsigned short g_W2h[512 * 512];         // fp16 of W2
__device__ __align__(16) unsigned short g_Hh[(size_t)MROWS * 512]; // fp16 of H (65 MB)

// ---------------------------------------------------------------------------
// Helpers
// ---------------------------------------------------------------------------
__device__ __forceinline__ uint32_t smem_u32(const void* p) {
    uint32_t a;
    asm("{ .reg .u64 t; cvta.to.shared.u64 t, %1; cvt.u32.u64 %0, t; }"
        : "=r"(a) : "l"(p));
    return a;
}
__device__ __forceinline__ void ldsm_x4(uint32_t* r, uint32_t addr) {
    asm volatile("ldmatrix.sync.aligned.m8n8.x4.shared.b16 {%0,%1,%2,%3},[%4];"
        : "=r"(r[0]), "=r"(r[1]), "=r"(r[2]), "=r"(r[3]) : "r"(addr));
}
__device__ __forceinline__ void ldsm_x2(uint32_t* r, uint32_t addr) {
    asm volatile("ldmatrix.sync.aligned.m8n8.x2.shared.b16 {%0,%1},[%2];"
        : "=r"(r[0]), "=r"(r[1]) : "r"(addr));
}
__device__ __forceinline__ void mma_bf16(float* d, const uint32_t* a, const uint32_t* b) {
    asm volatile(
        "mma.sync.aligned.m16n8k16.row.col.f32.bf16.bf16.f32 "
        "{%0,%1,%2,%3},{%4,%5,%6,%7},{%8,%9},{%0,%1,%2,%3};"
        : "+f"(d[0]), "+f"(d[1]), "+f"(d[2]), "+f"(d[3])
        : "r"(a[0]), "r"(a[1]), "r"(a[2]), "r"(a[3]), "r"(b[0]), "r"(b[1]));
}
__device__ __forceinline__ void mma_f16(float* d, const uint32_t* a, const uint32_t* b) {
    asm volatile(
        "mma.sync.aligned.m16n8k16.row.col.f32.f16.f16.f32 "
        "{%0,%1,%2,%3},{%4,%5,%6,%7},{%8,%9},{%0,%1,%2,%3};"
        : "+f"(d[0]), "+f"(d[1]), "+f"(d[2]), "+f"(d[3])
        : "r"(a[0]), "r"(a[1]), "r"(a[2]), "r"(a[3]), "r"(b[0]), "r"(b[1]));
}
__device__ __forceinline__ void cp_async16(uint32_t dst, const void* src) {
    asm volatile("cp.async.cg.shared.global [%0], [%1], 16;"
        :: "r"(dst), "l"(__cvta_generic_to_global(src)) : "memory");
}
#define CP_COMMIT() asm volatile("cp.async.commit_group;" ::: "memory")
#define CP_WAIT(n)  asm volatile("cp.async.wait_group %0;" :: "n"(n) : "memory")

// bf16 hi/lo split of two floats -> two packed bf16x2 words
__device__ __forceinline__ void split2(float x0, float x1, uint32_t& h, uint32_t& l) {
    __nv_bfloat16 h0 = __float2bfloat16(x0);
    __nv_bfloat16 h1 = __float2bfloat16(x1);
    h = (uint32_t)__bfloat16_as_ushort(h0) | ((uint32_t)__bfloat16_as_ushort(h1) << 16);
    __nv_bfloat16 l0 = __float2bfloat16(x0 - __bfloat162float(h0));
    __nv_bfloat16 l1 = __float2bfloat16(x1 - __bfloat162float(h1));
    l = (uint32_t)__bfloat16_as_ushort(l0) | ((uint32_t)__bfloat16_as_ushort(l1) << 16);
}

// ---------------------------------------------------------------------------
// Input split kernels
// ---------------------------------------------------------------------------
__global__ __launch_bounds__(256)
void k_w2half(const float* __restrict__ W2)
{
    int idx = blockIdx.x * 256 + threadIdx.x;         // 65536 float4s
    float4 v = reinterpret_cast<const float4*>(W2)[idx];
    __half2 a = __floats2half2_rn(v.x, v.y);
    __half2 b = __floats2half2_rn(v.z, v.w);
    reinterpret_cast<uint2*>(g_W2h)[idx] =
        make_uint2(*reinterpret_cast<uint32_t*>(&a), *reinterpret_cast<uint32_t*>(&b));
}

__global__ __launch_bounds__(256)
void k_fsplit(const float* __restrict__ F)
{
    int idx = blockIdx.x * 256 + threadIdx.x;         // 262144 float4s
    float4 v = reinterpret_cast<const float4*>(F)[idx];
    uint32_t h0, l0, h1, l1;
    split2(v.x, v.y, h0, l0);
    split2(v.z, v.w, h1, l1);
    reinterpret_cast<uint2*>(g_Fh)[idx] = make_uint2(h0, h1);
    reinterpret_cast<uint2*>(g_Fl)[idx] = make_uint2(l0, l1);
}

// W1' [c][k] = W1[c&511][(c>>9)*512 + k],  c<1024, k<512
__global__ __launch_bounds__(256)
void k_w1split(const float* __restrict__ W1)
{
    int idx = blockIdx.x * 256 + threadIdx.x;         // 131072 float4s
    int L = idx * 4;
    int c = L >> 9;
    int k = L & 511;
    const float4 v = *reinterpret_cast<const float4*>(
        W1 + (size_t)(c & 511) * 1024 + ((c >> 9) << 9) + k);
    uint32_t h0, l0, h1, l1;
    split2(v.x, v.y, h0, l0);
    split2(v.z, v.w, h1, l1);
    reinterpret_cast<uint2*>(g_W1h)[idx] = make_uint2(h0, h1);
    reinterpret_cast<uint2*>(g_W1l)[idx] = make_uint2(l0, l1);
}

// ---------------------------------------------------------------------------
// H: H[r][k] = fp16(relu(P[b*32+i][k] + P[b*32+j][512+k]))
// 8 warps per block, one row per warp, 16 elems per lane.
// ---------------------------------------------------------------------------
__global__ __launch_bounds__(256)
void k_hsplit()
{
    const int r   = blockIdx.x * 8 + (threadIdx.x >> 5);
    const int lid = threadIdx.x & 31;
    const int b = r / NPAIR;
    const int p = r - b * NPAIR;
    const int i = p / 31;
    const int jj = p - i * 31;
    const int j = jj + (jj >= i ? 1 : 0);

    const float* p1 = g_P + (size_t)(b * NDIM + i) * 1024 + lid * 16;
    const float* p2 = g_P + (size_t)(b * NDIM + j) * 1024 + 512 + lid * 16;
    unsigned short* hh = g_Hh + (size_t)r * 512 + lid * 16;

#pragma unroll
    for (int g = 0; g < 2; ++g) {                     // 2 groups of 8 elems
        float4 a0 = *reinterpret_cast<const float4*>(p1 + g * 8);
        float4 a1 = *reinterpret_cast<const float4*>(p1 + g * 8 + 4);
        float4 c0 = *reinterpret_cast<const float4*>(p2 + g * 8);
        float4 c1 = *reinterpret_cast<const float4*>(p2 + g * 8 + 4);
        __half2 h0 = __floats2half2_rn(fmaxf(a0.x + c0.x, 0.f), fmaxf(a0.y + c0.y, 0.f));
        __half2 h1 = __floats2half2_rn(fmaxf(a0.z + c0.z, 0.f), fmaxf(a0.w + c0.w, 0.f));
        __half2 h2 = __floats2half2_rn(fmaxf(a1.x + c1.x, 0.f), fmaxf(a1.y + c1.y, 0.f));
        __half2 h3 = __floats2half2_rn(fmaxf(a1.z + c1.z, 0.f), fmaxf(a1.w + c1.w, 0.f));
        uint4 H;
        H.x = *reinterpret_cast<uint32_t*>(&h0);
        H.y = *reinterpret_cast<uint32_t*>(&h1);
        H.z = *reinterpret_cast<uint32_t*>(&h2);
        H.w = *reinterpret_cast<uint32_t*>(&h3);
        *reinterpret_cast<uint4*>(hh + g * 8) = H;
    }
}

// ---------------------------------------------------------------------------
// GEMM A: P = F @ W1'^T (+ b1 on first 512 cols). M=2048, N=1024, K=512.
// 3-term split-bf16, 3-stage cp.async (measured 23us).
// ---------------------------------------------------------------------------
#define STG_A    65536
#define SMEM_A3  (3 * STG_A + 1024)

__global__ __launch_bounds__(256, 1)
void k_gemmA(const unsigned short* __restrict__ Ah_g,
             const unsigned short* __restrict__ Al_g,
             const unsigned short* __restrict__ Bh_g,
             const unsigned short* __restrict__ Bl_g,
             const float* __restrict__ bias,
             float* __restrict__ out)
{
    extern __shared__ char dsm[];
    const int tid = threadIdx.x;
    const int wid = tid >> 5;
    const int lid = tid & 31;

    uint32_t raw = smem_u32(dsm);
    const uint32_t dbase = (raw + 1023u) & ~1023u;

    const int rowBase = blockIdx.y * 128;
    const int colBase = blockIdx.x * 128;

    const unsigned short* Asrc_h = Ah_g + (size_t)rowBase * 512;
    const unsigned short* Asrc_l = Al_g + (size_t)rowBase * 512;
    const unsigned short* Bsrc_h = Bh_g + (size_t)colBase * 512;
    const unsigned short* Bsrc_l = Bl_g + (size_t)colBase * 512;

    auto ldt = [&](uint32_t dst, const unsigned short* src, int c) {
#pragma unroll
        for (int g = 0; g < 4; ++g) {
            const int q = tid + 256 * g;
            const int row = q >> 3;
            const int kb  = q & 7;
            const uint32_t off = (uint32_t)row * 128 + (uint32_t)((kb ^ (row & 7)) << 4);
            cp_async16(dst + off, src + (size_t)row * 512 + c * 64 + kb * 8);
        }
    };
    auto loadStage = [&](int c, int s) {
        const uint32_t st = dbase + s * STG_A;
        ldt(st,         Asrc_h, c);
        ldt(st + 16384, Asrc_l, c);
        ldt(st + 32768, Bsrc_h, c);
        ldt(st + 49152, Bsrc_l, c);
    };

    const int wm = (wid & 3) * 32;
    const int wn = (wid >> 2) * 64;

    float acc[2][8][4];
#pragma unroll
    for (int mi = 0; mi < 2; ++mi)
#pragma unroll
        for (int ni = 0; ni < 8; ++ni)
#pragma unroll
            for (int q = 0; q < 4; ++q) acc[mi][ni][q] = 0.0f;

    auto compute = [&](int s) {
        const uint32_t AhB = dbase + s * STG_A;
        const uint32_t BhB = AhB + 32768;
        const int mrow = lid & 15;
        const int ksel = lid >> 4;
        const int bn_  = lid & 7;
        const int bsel = (lid >> 3) & 1;
#pragma unroll
        for (int ks = 0; ks < 4; ++ks) {
            uint32_t ah[2][4], al[2][4], bh[8][2], bl[8][2];
#pragma unroll
            for (int mi = 0; mi < 2; ++mi) {
                const uint32_t r = (uint32_t)(wm + mi * 16 + mrow);
                const uint32_t kb = (uint32_t)(ks * 2 + ksel);
                const uint32_t addr = AhB + r * 128 + ((kb ^ (r & 7)) << 4);
                ldsm_x4(ah[mi], addr);
                ldsm_x4(al[mi], addr + 16384);
            }
#pragma unroll
            for (int ni = 0; ni < 8; ++ni) {
                const uint32_t n = (uint32_t)(wn + ni * 8 + bn_);
                const uint32_t kb = (uint32_t)(ks * 2 + bsel);
                const uint32_t addr = BhB + n * 128 + ((kb ^ (n & 7)) << 4);
                ldsm_x2(bh[ni], addr);
                ldsm_x2(bl[ni], addr + 16384);
            }
#pragma unroll
            for (int mi = 0; mi < 2; ++mi)
#pragma unroll
                for (int ni = 0; ni < 8; ++ni) {
                    mma_bf16(acc[mi][ni], ah[mi], bh[ni]);
                    mma_bf16(acc[mi][ni], ah[mi], bl[ni]);
                    mma_bf16(acc[mi][ni], al[mi], bh[ni]);
                }
        }
    };

    loadStage(0, 0); CP_COMMIT();
    loadStage(1, 1); CP_COMMIT();

    for (int c = 0; c < 8; ++c) {
        CP_WAIT(1);
        __syncthreads();
        if (c + 2 < 8) loadStage(c + 2, (c + 2) % 3);
        CP_COMMIT();
        compute(c % 3);
    }

    // epilogue: bias only on first 512 columns (P1 half)
    {
        const int t2 = (lid & 3) * 2;
        const int gg = lid >> 2;
        float2 bb[8];
#pragma unroll
        for (int ni = 0; ni < 8; ++ni) {
            if (colBase < 512)
                bb[ni] = *reinterpret_cast<const float2*>(bias + colBase + wn + ni * 8 + t2);
            else
                bb[ni] = make_float2(0.f, 0.f);
        }
#pragma unroll
        for (int mi = 0; mi < 2; ++mi) {
            const int r0 = rowBase + wm + mi * 16 + gg;
#pragma unroll
            for (int ni = 0; ni < 8; ++ni) {
                const int cc = colBase + wn + ni * 8 + t2;
                float2 v0, v1;
                v0.x = acc[mi][ni][0] + bb[ni].x;
                v0.y = acc[mi][ni][1] + bb[ni].y;
                v1.x = acc[mi][ni][2] + bb[ni].x;
                v1.y = acc[mi][ni][3] + bb[ni].y;
                *reinterpret_cast<float2*>(out + (size_t)r0 * 1024 + cc) = v0;
                *reinterpret_cast<float2*>(out + (size_t)(r0 + 8) * 1024 + cc) = v1;
            }
        }
    }
}

// ---------------------------------------------------------------------------
// GEMM B: out = Hh @ W2h^T + b2   (single-term fp16, fp32 accumulate)
// M=63488, N=512, K=512. CTA 128x128, 8 warps 4x2, K in 8 chunks of 64.
// 3-stage cp.async; stage 32KB: Ah 16K | Bh 16K. 2 CTAs/SM.
// ---------------------------------------------------------------------------
#define STG_B    32768
#define SMEM_B3  (3 * STG_B + 1024)

__global__ __launch_bounds__(256, 2)
void k_gemmB(const float* __restrict__ b2, float* __restrict__ out)
{
    extern __shared__ char dsm[];
    const int tid = threadIdx.x;
    const int wid = tid >> 5;
    const int lid = tid & 31;

    uint32_t raw = smem_u32(dsm);
    const uint32_t dbase = (raw + 1023u) & ~1023u;

    const int rowBase = blockIdx.y * 128;
    const int colBase = blockIdx.x * 128;

    const unsigned short* Asrc_h = g_Hh + (size_t)rowBase * 512;
    const unsigned short* Bsrc_h = g_W2h + (size_t)colBase * 512;

    auto ldt = [&](uint32_t dst, const unsigned short* src, int c) {
#pragma unroll
        for (int g = 0; g < 4; ++g) {
            const int q = tid + 256 * g;
            const int row = q >> 3;
            const int kb  = q & 7;
            const uint32_t off = (uint32_t)row * 128 + (uint32_t)((kb ^ (row & 7)) << 4);
            cp_async16(dst + off, src + (size_t)row * 512 + c * 64 + kb * 8);
        }
    };
    auto loadStage = [&](int c, int s) {
        const uint32_t st = dbase + s * STG_B;
        ldt(st,         Asrc_h, c);
        ldt(st + 16384, Bsrc_h, c);
    };

    const int wm = (wid & 3) * 32;
    const int wn = (wid >> 2) * 64;

    float acc[2][8][4];
#pragma unroll
    for (int mi = 0; mi < 2; ++mi)
#pragma unroll
        for (int ni = 0; ni < 8; ++ni)
#pragma unroll
            for (int q = 0; q < 4; ++q) acc[mi][ni][q] = 0.0f;

    auto compute = [&](int s) {
        const uint32_t AhB = dbase + s * STG_B;
        const uint32_t BhB = AhB + 16384;
        const int mrow  = lid & 15;
        const int ksel  = lid >> 4;
        const int bn2   = lid & 7;
        const int khalf = (lid >> 3) & 1;
        const int tsel  = (lid >> 4) & 1;
#pragma unroll
        for (int ks = 0; ks < 4; ++ks) {
            uint32_t ah[2][4], bh[8][2];
#pragma unroll
            for (int mi = 0; mi < 2; ++mi) {
                const uint32_t r = (uint32_t)(wm + mi * 16 + mrow);
                const uint32_t kb = (uint32_t)(ks * 2 + ksel);
                const uint32_t addr = AhB + r * 128 + ((kb ^ (r & 7)) << 4);
                ldsm_x4(ah[mi], addr);
            }
            // B: each ldmatrix x4 grabs 2 n-tiles x 2 k-halves
#pragma unroll
            for (int nip = 0; nip < 4; ++nip) {
                const uint32_t n = (uint32_t)(wn + (nip * 2 + tsel) * 8 + bn2);
                const uint32_t kb = (uint32_t)(ks * 2 + khalf);
                const uint32_t addr = BhB + n * 128 + ((kb ^ (n & 7)) << 4);
                uint32_t t[4];
                ldsm_x4(t, addr);
                bh[2 * nip][0] = t[0]; bh[2 * nip][1] = t[1];
                bh[2 * nip + 1][0] = t[2]; bh[2 * nip + 1][1] = t[3];
            }
#pragma unroll
            for (int mi = 0; mi < 2; ++mi)
#pragma unroll
                for (int ni = 0; ni < 8; ++ni)
                    mma_f16(acc[mi][ni], ah[mi], bh[ni]);
        }
    };

    loadStage(0, 0); CP_COMMIT();
    loadStage(1, 1); CP_COMMIT();

    for (int c = 0; c < 8; ++c) {
        CP_WAIT(1);
        __syncthreads();
        if (c + 2 < 8) loadStage(c + 2, (c + 2) % 3);
        CP_COMMIT();
        compute(c % 3);
    }

    // epilogue
    {
        const int t2 = (lid & 3) * 2;
        const int gg = lid >> 2;
        float2 bb[8];
#pragma unroll
        for (int ni = 0; ni < 8; ++ni)
            bb[ni] = *reinterpret_cast<const float2*>(b2 + colBase + wn + ni * 8 + t2);

#pragma unroll
        for (int mi = 0; mi < 2; ++mi) {
            const int r0 = rowBase + wm + mi * 16 + gg;
#pragma unroll
            for (int ni = 0; ni < 8; ++ni) {
                const int cc = colBase + wn + ni * 8 + t2;
                float2 v0, v1;
                v0.x = acc[mi][ni][0] + bb[ni].x;
                v0.y = acc[mi][ni][1] + bb[ni].y;
                v1.x = acc[mi][ni][2] + bb[ni].x;
                v1.y = acc[mi][ni][3] + bb[ni].y;
                *reinterpret_cast<float2*>(out + (size_t)r0 * 512 + cc) = v0;
                *reinterpret_cast<float2*>(out + (size_t)(r0 + 8) * 512 + cc) = v1;
            }
        }
    }
}

// ---------------------------------------------------------------------------
extern "C" void kernel_launch(void* const* d_in, const int* in_sizes, int n_in,
                              void* d_out, int out_size)
{
    const float* F  = (const float*)d_in[0];   // person_feats (64,32,512)
    const float* W1 = (const float*)d_in[1];   // (512, 1024)
    const float* b1 = (const float*)d_in[2];   // (512,)
    const float* W2 = (const float*)d_in[3];   // (512, 512)
    const float* b2 = (const float*)d_in[4];   // (512,)
    float* out = (float*)d_out;                // (64, 992, 512)

    cudaFuncSetAttribute(k_gemmA, cudaFuncAttributeMaxDynamicSharedMemorySize, SMEM_A3);
    cudaFuncSetAttribute(k_gemmB, cudaFuncAttributeMaxDynamicSharedMemorySize, SMEM_B3);

    unsigned short *Fh, *Fl, *W1h, *W1l;
    float* P;
    cudaGetSymbolAddress((void**)&Fh,  g_Fh);
    cudaGetSymbolAddress((void**)&Fl,  g_Fl);
    cudaGetSymbolAddress((void**)&W1h, g_W1h);
    cudaGetSymbolAddress((void**)&W1l, g_W1l);
    cudaGetSymbolAddress((void**)&P,   g_P);

    // 1) split inputs (W2 -> fp16; F/W1 -> bf16 hi/lo)
    k_w2half<<<256, 256>>>(W2);
    k_fsplit<<<1024, 256>>>(F);
    k_w1split<<<512, 256>>>(W1);

    // 2) P = F @ W1'^T (+ b1 on first 512 cols): M=2048, N=1024
    {
        dim3 g(8, 16);
        k_gemmA<<<g, 256, SMEM_A3>>>(Fh, Fl, W1h, W1l, b1, P);
    }

    // 3) H = fp16(relu(P1 + P2))
    k_hsplit<<<MROWS / 8, 256>>>();

    // 4) out = Hh @ W2h^T + b2: M=63488, N=512
    {
        dim3 g(4, MROWS / 128);
        k_gemmB<<<g, 256, SMEM_B3>>>(b2, out);
    }
}

// round 10
// speedup vs baseline: 4.4963x; 1.0914x over previous
#include <cuda_runtime.h>
#include <cuda_fp16.h>
#include <cstdint>

// ---------------------------------------------------------------------------
// Problem constants
#define BDIM   64
#define NDIM   32
#define DDIM   512
#define NPAIR  992                 // 32*31 ordered pairs
#define MROWS  (BDIM * NPAIR)      // 63488 output rows
#define BNROWS (BDIM * NDIM)       // 2048 person rows

// Scratch (device globals; no allocations allowed)
__device__ float g_P[(size_t)BNROWS * 1024];                       // 8 MB fp32 partials
__device__ __align__(16) unsigned short g_Fh[BNROWS * 512];        // fp16 of F
__device__ __align__(16) unsigned short g_W1h[1024 * 512];         // fp16 W1 rearranged [c][k]
__device__ __align__(16) unsigned short g_W2h[512 * 512];          // fp16 of W2
__device__ __align__(16) unsigned short g_Hh[(size_t)MROWS * 512]; // fp16 of H (65 MB)

// ---------------------------------------------------------------------------
// Helpers
// ---------------------------------------------------------------------------
__device__ __forceinline__ uint32_t smem_u32(const void* p) {
    uint32_t a;
    asm("{ .reg .u64 t; cvta.to.shared.u64 t, %1; cvt.u32.u64 %0, t; }"
        : "=r"(a) : "l"(p));
    return a;
}
__device__ __forceinline__ void ldsm_x4(uint32_t* r, uint32_t addr) {
    asm volatile("ldmatrix.sync.aligned.m8n8.x4.shared.b16 {%0,%1,%2,%3},[%4];"
        : "=r"(r[0]), "=r"(r[1]), "=r"(r[2]), "=r"(r[3]) : "r"(addr));
}
__device__ __forceinline__ void mma_f16(float* d, const uint32_t* a, const uint32_t* b) {
    asm volatile(
        "mma.sync.aligned.m16n8k16.row.col.f32.f16.f16.f32 "
        "{%0,%1,%2,%3},{%4,%5,%6,%7},{%8,%9},{%0,%1,%2,%3};"
        : "+f"(d[0]), "+f"(d[1]), "+f"(d[2]), "+f"(d[3])
        : "r"(a[0]), "r"(a[1]), "r"(a[2]), "r"(a[3]), "r"(b[0]), "r"(b[1]));
}
__device__ __forceinline__ void cp_async16(uint32_t dst, const void* src) {
    asm volatile("cp.async.cg.shared.global [%0], [%1], 16;"
        :: "r"(dst), "l"(__cvta_generic_to_global(src)) : "memory");
}
#define CP_COMMIT() asm volatile("cp.async.commit_group;" ::: "memory")
#define CP_WAIT(n)  asm volatile("cp.async.wait_group %0;" :: "n"(n) : "memory")

__device__ __forceinline__ uint2 f4_to_h4(float4 v) {
    __half2 a = __floats2half2_rn(v.x, v.y);
    __half2 b = __floats2half2_rn(v.z, v.w);
    return make_uint2(*reinterpret_cast<uint32_t*>(&a), *reinterpret_cast<uint32_t*>(&b));
}

// ---------------------------------------------------------------------------
// k_prep: all input conversions in one launch.
//   [0, 262144)            : F (1M floats)           -> g_Fh fp16
//   [262144, 393216)       : W1 rearranged [c][k]    -> g_W1h fp16
//   [393216, 458752)       : W2                      -> g_W2h fp16
// ---------------------------------------------------------------------------
__global__ __launch_bounds__(256)
void k_prep(const float* __restrict__ F, const float* __restrict__ W1,
            const float* __restrict__ W2)
{
    int idx = blockIdx.x * 256 + threadIdx.x;
    if (idx < 262144) {
        float4 v = reinterpret_cast<const float4*>(F)[idx];
        reinterpret_cast<uint2*>(g_Fh)[idx] = f4_to_h4(v);
    } else if (idx < 393216) {
        int i = idx - 262144;
        int L = i * 4;
        int c = L >> 9;
        int k = L & 511;
        float4 v = *reinterpret_cast<const float4*>(
            W1 + (size_t)(c & 511) * 1024 + ((c >> 9) << 9) + k);
        reinterpret_cast<uint2*>(g_W1h)[i] = f4_to_h4(v);
    } else {
        int i = idx - 393216;
        float4 v = reinterpret_cast<const float4*>(W2)[i];
        reinterpret_cast<uint2*>(g_W2h)[i] = f4_to_h4(v);
    }
}

// ---------------------------------------------------------------------------
// H: H[r][k] = fp16(relu(P[b*32+i][k] + P[b*32+j][512+k]))
// 8 warps per block, one row per warp, 16 elems per lane.
// ---------------------------------------------------------------------------
__global__ __launch_bounds__(256)
void k_hsplit()
{
    const int r   = blockIdx.x * 8 + (threadIdx.x >> 5);
    const int lid = threadIdx.x & 31;
    const int b = r / NPAIR;
    const int p = r - b * NPAIR;
    const int i = p / 31;
    const int jj = p - i * 31;
    const int j = jj + (jj >= i ? 1 : 0);

    const float* p1 = g_P + (size_t)(b * NDIM + i) * 1024 + lid * 16;
    const float* p2 = g_P + (size_t)(b * NDIM + j) * 1024 + 512 + lid * 16;
    unsigned short* hh = g_Hh + (size_t)r * 512 + lid * 16;

#pragma unroll
    for (int g = 0; g < 2; ++g) {                     // 2 groups of 8 elems
        float4 a0 = *reinterpret_cast<const float4*>(p1 + g * 8);
        float4 a1 = *reinterpret_cast<const float4*>(p1 + g * 8 + 4);
        float4 c0 = *reinterpret_cast<const float4*>(p2 + g * 8);
        float4 c1 = *reinterpret_cast<const float4*>(p2 + g * 8 + 4);
        float4 r0 = make_float4(fmaxf(a0.x + c0.x, 0.f), fmaxf(a0.y + c0.y, 0.f),
                                fmaxf(a0.z + c0.z, 0.f), fmaxf(a0.w + c0.w, 0.f));
        float4 r1 = make_float4(fmaxf(a1.x + c1.x, 0.f), fmaxf(a1.y + c1.y, 0.f),
                                fmaxf(a1.z + c1.z, 0.f), fmaxf(a1.w + c1.w, 0.f));
        uint2 H0 = f4_to_h4(r0);
        uint2 H1 = f4_to_h4(r1);
        uint4 H = make_uint4(H0.x, H0.y, H1.x, H1.y);
        *reinterpret_cast<uint4*>(hh + g * 8) = H;
    }
}

// ---------------------------------------------------------------------------
// k_gemm16: single-term fp16 GEMM, fp32 accumulate.
//   out[r, n] = A[r,:] @ B[n,:] + bias
// A: [M][512] fp16 row-major, B: [N][512] fp16 row-major.
// CTA 128x128, 8 warps 4(M)x2(N), K in 8 chunks of 64.
// 3-stage cp.async; stage 32KB: A 16K | B 16K. 2 CTAs/SM.
// BIAS_MODE 1: bias only when colBase < 512 (gemmA). 2: always (gemmB).
// ---------------------------------------------------------------------------
#define STG_B    32768
#define SMEM_B3  (3 * STG_B + 1024)

template<int BIAS_MODE>
__global__ __launch_bounds__(256, 2)
void k_gemm16(const unsigned short* __restrict__ A_g,
              const unsigned short* __restrict__ B_g,
              const float* __restrict__ bias,
              float* __restrict__ out, int outStride)
{
    extern __shared__ char dsm[];
    const int tid = threadIdx.x;
    const int wid = tid >> 5;
    const int lid = tid & 31;

    uint32_t raw = smem_u32(dsm);
    const uint32_t dbase = (raw + 1023u) & ~1023u;

    const int rowBase = blockIdx.y * 128;
    const int colBase = blockIdx.x * 128;

    const unsigned short* Asrc = A_g + (size_t)rowBase * 512;
    const unsigned short* Bsrc = B_g + (size_t)colBase * 512;

    auto ldt = [&](uint32_t dst, const unsigned short* src, int c) {
#pragma unroll
        for (int g = 0; g < 4; ++g) {
            const int q = tid + 256 * g;
            const int row = q >> 3;
            const int kb  = q & 7;
            const uint32_t off = (uint32_t)row * 128 + (uint32_t)((kb ^ (row & 7)) << 4);
            cp_async16(dst + off, src + (size_t)row * 512 + c * 64 + kb * 8);
        }
    };
    auto loadStage = [&](int c, int s) {
        const uint32_t st = dbase + s * STG_B;
        ldt(st,         Asrc, c);
        ldt(st + 16384, Bsrc, c);
    };

    const int wm = (wid & 3) * 32;
    const int wn = (wid >> 2) * 64;

    float acc[2][8][4];
#pragma unroll
    for (int mi = 0; mi < 2; ++mi)
#pragma unroll
        for (int ni = 0; ni < 8; ++ni)
#pragma unroll
            for (int q = 0; q < 4; ++q) acc[mi][ni][q] = 0.0f;

    auto compute = [&](int s) {
        const uint32_t AhB = dbase + s * STG_B;
        const uint32_t BhB = AhB + 16384;
        const int mrow  = lid & 15;
        const int ksel  = lid >> 4;
        const int bn2   = lid & 7;
        const int khalf = (lid >> 3) & 1;
        const int tsel  = (lid >> 4) & 1;
#pragma unroll
        for (int ks = 0; ks < 4; ++ks) {
            uint32_t ah[2][4], bh[8][2];
#pragma unroll
            for (int mi = 0; mi < 2; ++mi) {
                const uint32_t r = (uint32_t)(wm + mi * 16 + mrow);
                const uint32_t kb = (uint32_t)(ks * 2 + ksel);
                const uint32_t addr = AhB + r * 128 + ((kb ^ (r & 7)) << 4);
                ldsm_x4(ah[mi], addr);
            }
            // B: each ldmatrix x4 grabs 2 n-tiles x 2 k-halves
#pragma unroll
            for (int nip = 0; nip < 4; ++nip) {
                const uint32_t n = (uint32_t)(wn + (nip * 2 + tsel) * 8 + bn2);
                const uint32_t kb = (uint32_t)(ks * 2 + khalf);
                const uint32_t addr = BhB + n * 128 + ((kb ^ (n & 7)) << 4);
                uint32_t t[4];
                ldsm_x4(t, addr);
                bh[2 * nip][0] = t[0]; bh[2 * nip][1] = t[1];
                bh[2 * nip + 1][0] = t[2]; bh[2 * nip + 1][1] = t[3];
            }
#pragma unroll
            for (int mi = 0; mi < 2; ++mi)
#pragma unroll
                for (int ni = 0; ni < 8; ++ni)
                    mma_f16(acc[mi][ni], ah[mi], bh[ni]);
        }
    };

    loadStage(0, 0); CP_COMMIT();
    loadStage(1, 1); CP_COMMIT();

    for (int c = 0; c < 8; ++c) {
        CP_WAIT(1);
        __syncthreads();
        if (c + 2 < 8) loadStage(c + 2, (c + 2) % 3);
        CP_COMMIT();
        compute(c % 3);
    }

    // epilogue
    {
        const int t2 = (lid & 3) * 2;
        const int gg = lid >> 2;
        float2 bb[8];
#pragma unroll
        for (int ni = 0; ni < 8; ++ni) {
            if (BIAS_MODE == 2 || colBase < 512)
                bb[ni] = *reinterpret_cast<const float2*>(bias + colBase + wn + ni * 8 + t2);
            else
                bb[ni] = make_float2(0.f, 0.f);
        }
#pragma unroll
        for (int mi = 0; mi < 2; ++mi) {
            const int r0 = rowBase + wm + mi * 16 + gg;
#pragma unroll
            for (int ni = 0; ni < 8; ++ni) {
                const int cc = colBase + wn + ni * 8 + t2;
                float2 v0, v1;
                v0.x = acc[mi][ni][0] + bb[ni].x;
                v0.y = acc[mi][ni][1] + bb[ni].y;
                v1.x = acc[mi][ni][2] + bb[ni].x;
                v1.y = acc[mi][ni][3] + bb[ni].y;
                *reinterpret_cast<float2*>(out + (size_t)r0 * outStride + cc) = v0;
                *reinterpret_cast<float2*>(out + (size_t)(r0 + 8) * outStride + cc) = v1;
            }
        }
    }
}

// ---------------------------------------------------------------------------
extern "C" void kernel_launch(void* const* d_in, const int* in_sizes, int n_in,
                              void* d_out, int out_size)
{
    const float* F  = (const float*)d_in[0];   // person_feats (64,32,512)
    const float* W1 = (const float*)d_in[1];   // (512, 1024)
    const float* b1 = (const float*)d_in[2];   // (512,)
    const float* W2 = (const float*)d_in[3];   // (512, 512)
    const float* b2 = (const float*)d_in[4];   // (512,)
    float* out = (float*)d_out;                // (64, 992, 512)

    cudaFuncSetAttribute(k_gemm16<1>, cudaFuncAttributeMaxDynamicSharedMemorySize, SMEM_B3);
    cudaFuncSetAttribute(k_gemm16<2>, cudaFuncAttributeMaxDynamicSharedMemorySize, SMEM_B3);

    unsigned short *Fh, *W1h, *W2h, *Hh;
    float* P;
    cudaGetSymbolAddress((void**)&Fh,  g_Fh);
    cudaGetSymbolAddress((void**)&W1h, g_W1h);
    cudaGetSymbolAddress((void**)&W2h, g_W2h);
    cudaGetSymbolAddress((void**)&Hh,  g_Hh);
    cudaGetSymbolAddress((void**)&P,   g_P);

    // 1) convert all inputs to fp16 in one launch
    k_prep<<<1792, 256>>>(F, W1, W2);

    // 2) P = F @ W1'^T (+ b1 on first 512 cols): M=2048, N=1024
    {
        dim3 g(8, 16);
        k_gemm16<1><<<g, 256, SMEM_B3>>>(Fh, W1h, b1, P, 1024);
    }

    // 3) H = fp16(relu(P1 + P2))
    k_hsplit<<<MROWS / 8, 256>>>();

    // 4) out = Hh @ W2h^T + b2: M=63488, N=512
    {
        dim3 g(4, MROWS / 128);
        k_gemm16<2><<<g, 256, SMEM_B3>>>(Hh, W2h, b2, out, 512);
    }
}

// round 11
// speedup vs baseline: 4.6849x; 1.0420x over previous
#include <cuda_runtime.h>
#include <cuda_fp16.h>
#include <cstdint>

// ---------------------------------------------------------------------------
// Problem constants
#define BDIM   64
#define NDIM   32
#define DDIM   512
#define NPAIR  992                 // 32*31 ordered pairs
#define MROWS  (BDIM * NPAIR)      // 63488 output rows
#define BNROWS (BDIM * NDIM)       // 2048 person rows

// Scratch (device globals; no allocations allowed)
__device__ float g_P[(size_t)BNROWS * 1024];                       // 8 MB fp32 partials
__device__ __align__(16) unsigned short g_Fh[BNROWS * 512];        // fp16 of F
__device__ __align__(16) unsigned short g_W1h[1024 * 512];         // fp16 W1 rearranged [c][k]
__device__ __align__(16) unsigned short g_W2h[512 * 512];          // fp16 of W2
__device__ __align__(16) unsigned short g_Hh[(size_t)MROWS * 512]; // fp16 of H (65 MB)

// ---------------------------------------------------------------------------
// Helpers
// ---------------------------------------------------------------------------
__device__ __forceinline__ uint32_t smem_u32(const void* p) {
    uint32_t a;
    asm("{ .reg .u64 t; cvta.to.shared.u64 t, %1; cvt.u32.u64 %0, t; }"
        : "=r"(a) : "l"(p));
    return a;
}
__device__ __forceinline__ void ldsm_x4(uint32_t* r, uint32_t addr) {
    asm volatile("ldmatrix.sync.aligned.m8n8.x4.shared.b16 {%0,%1,%2,%3},[%4];"
        : "=r"(r[0]), "=r"(r[1]), "=r"(r[2]), "=r"(r[3]) : "r"(addr));
}
__device__ __forceinline__ void mma_f16(float* d, const uint32_t* a, const uint32_t* b) {
    asm volatile(
        "mma.sync.aligned.m16n8k16.row.col.f32.f16.f16.f32 "
        "{%0,%1,%2,%3},{%4,%5,%6,%7},{%8,%9},{%0,%1,%2,%3};"
        : "+f"(d[0]), "+f"(d[1]), "+f"(d[2]), "+f"(d[3])
        : "r"(a[0]), "r"(a[1]), "r"(a[2]), "r"(a[3]), "r"(b[0]), "r"(b[1]));
}
__device__ __forceinline__ void cp_async16(uint32_t dst, const void* src) {
    asm volatile("cp.async.cg.shared.global [%0], [%1], 16;"
        :: "r"(dst), "l"(__cvta_generic_to_global(src)) : "memory");
}
#define CP_COMMIT() asm volatile("cp.async.commit_group;" ::: "memory")
#define CP_WAIT(n)  asm volatile("cp.async.wait_group %0;" :: "n"(n) : "memory")

__device__ __forceinline__ uint2 f4_to_h4(float4 v) {
    __half2 a = __floats2half2_rn(v.x, v.y);
    __half2 b = __floats2half2_rn(v.z, v.w);
    return make_uint2(*reinterpret_cast<uint32_t*>(&a), *reinterpret_cast<uint32_t*>(&b));
}

// ---------------------------------------------------------------------------
// k_prep: all input conversions in one launch.
// ---------------------------------------------------------------------------
__global__ __launch_bounds__(256)
void k_prep(const float* __restrict__ F, const float* __restrict__ W1,
            const float* __restrict__ W2)
{
    int idx = blockIdx.x * 256 + threadIdx.x;
    if (idx < 262144) {
        float4 v = reinterpret_cast<const float4*>(F)[idx];
        reinterpret_cast<uint2*>(g_Fh)[idx] = f4_to_h4(v);
    } else if (idx < 393216) {
        int i = idx - 262144;
        int L = i * 4;
        int c = L >> 9;
        int k = L & 511;
        float4 v = *reinterpret_cast<const float4*>(
            W1 + (size_t)(c & 511) * 1024 + ((c >> 9) << 9) + k);
        reinterpret_cast<uint2*>(g_W1h)[i] = f4_to_h4(v);
    } else {
        int i = idx - 393216;
        float4 v = reinterpret_cast<const float4*>(W2)[i];
        reinterpret_cast<uint2*>(g_W2h)[i] = f4_to_h4(v);
    }
}

// ---------------------------------------------------------------------------
// H: H[r][k] = fp16(relu(P[b*32+i][k] + P[b*32+j][512+k]))
// ---------------------------------------------------------------------------
__global__ __launch_bounds__(256)
void k_hsplit()
{
    const int r   = blockIdx.x * 8 + (threadIdx.x >> 5);
    const int lid = threadIdx.x & 31;
    const int b = r / NPAIR;
    const int p = r - b * NPAIR;
    const int i = p / 31;
    const int jj = p - i * 31;
    const int j = jj + (jj >= i ? 1 : 0);

    const float* p1 = g_P + (size_t)(b * NDIM + i) * 1024 + lid * 16;
    const float* p2 = g_P + (size_t)(b * NDIM + j) * 1024 + 512 + lid * 16;
    unsigned short* hh = g_Hh + (size_t)r * 512 + lid * 16;

#pragma unroll
    for (int g = 0; g < 2; ++g) {
        float4 a0 = *reinterpret_cast<const float4*>(p1 + g * 8);
        float4 a1 = *reinterpret_cast<const float4*>(p1 + g * 8 + 4);
        float4 c0 = *reinterpret_cast<const float4*>(p2 + g * 8);
        float4 c1 = *reinterpret_cast<const float4*>(p2 + g * 8 + 4);
        float4 r0 = make_float4(fmaxf(a0.x + c0.x, 0.f), fmaxf(a0.y + c0.y, 0.f),
                                fmaxf(a0.z + c0.z, 0.f), fmaxf(a0.w + c0.w, 0.f));
        float4 r1 = make_float4(fmaxf(a1.x + c1.x, 0.f), fmaxf(a1.y + c1.y, 0.f),
                                fmaxf(a1.z + c1.z, 0.f), fmaxf(a1.w + c1.w, 0.f));
        uint2 H0 = f4_to_h4(r0);
        uint2 H1 = f4_to_h4(r1);
        uint4 H = make_uint4(H0.x, H0.y, H1.x, H1.y);
        *reinterpret_cast<uint4*>(hh + g * 8) = H;
    }
}

// ---------------------------------------------------------------------------
// k_gemm16: single-term fp16 GEMM, fp32 accumulate.
//   out[r, n] = A[r,:] @ B[n,:] + bias
// CTA 128x128, 128 threads = 4 warps in 2(M)x2(N) grid of 64x64 warp tiles.
// K = 8 chunks of 64. 3-stage cp.async; stage 32KB: A 16K | B 16K.
// 2 CTAs/SM. smem reads/chunk: A 2x + B 2x = 64KB (was 96KB with 8 warps).
// BIAS_MODE 1: bias only when colBase < 512 (gemmA). 2: always (gemmB).
// ---------------------------------------------------------------------------
#define STG_B    32768
#define SMEM_B3  (3 * STG_B + 1024)

template<int BIAS_MODE>
__global__ __launch_bounds__(128, 2)
void k_gemm16(const unsigned short* __restrict__ A_g,
              const unsigned short* __restrict__ B_g,
              const float* __restrict__ bias,
              float* __restrict__ out, int outStride)
{
    extern __shared__ char dsm[];
    const int tid = threadIdx.x;
    const int wid = tid >> 5;
    const int lid = tid & 31;

    uint32_t raw = smem_u32(dsm);
    const uint32_t dbase = (raw + 1023u) & ~1023u;

    const int rowBase = blockIdx.y * 128;
    const int colBase = blockIdx.x * 128;

    const unsigned short* Asrc = A_g + (size_t)rowBase * 512;
    const unsigned short* Bsrc = B_g + (size_t)colBase * 512;

    // one 128x64 fp16 tile = 1024 16B chunks; 128 threads x 8
    auto ldt = [&](uint32_t dst, const unsigned short* src, int c) {
#pragma unroll
        for (int g = 0; g < 8; ++g) {
            const int q = tid + 128 * g;
            const int row = q >> 3;
            const int kb  = q & 7;
            const uint32_t off = (uint32_t)row * 128 + (uint32_t)((kb ^ (row & 7)) << 4);
            cp_async16(dst + off, src + (size_t)row * 512 + c * 64 + kb * 8);
        }
    };
    auto loadStage = [&](int c, int s) {
        const uint32_t st = dbase + s * STG_B;
        ldt(st,         Asrc, c);
        ldt(st + 16384, Bsrc, c);
    };

    const int wm = (wid & 1) * 64;     // warp M offset (2 rows of warps)
    const int wn = (wid >> 1) * 64;    // warp N offset (2 cols of warps)

    float acc[4][8][4];
#pragma unroll
    for (int mi = 0; mi < 4; ++mi)
#pragma unroll
        for (int ni = 0; ni < 8; ++ni)
#pragma unroll
            for (int q = 0; q < 4; ++q) acc[mi][ni][q] = 0.0f;

    auto compute = [&](int s) {
        const uint32_t AhB = dbase + s * STG_B;
        const uint32_t BhB = AhB + 16384;
        const int mrow  = lid & 15;
        const int ksel  = lid >> 4;
        const int bn2   = lid & 7;
        const int khalf = (lid >> 3) & 1;
        const int tsel  = (lid >> 4) & 1;
#pragma unroll
        for (int ks = 0; ks < 4; ++ks) {
            uint32_t ah[4][4], bh[8][2];
#pragma unroll
            for (int mi = 0; mi < 4; ++mi) {
                const uint32_t r = (uint32_t)(wm + mi * 16 + mrow);
                const uint32_t kb = (uint32_t)(ks * 2 + ksel);
                const uint32_t addr = AhB + r * 128 + ((kb ^ (r & 7)) << 4);
                ldsm_x4(ah[mi], addr);
            }
            // B: each ldmatrix x4 grabs 2 n-tiles x 2 k-halves
#pragma unroll
            for (int nip = 0; nip < 4; ++nip) {
                const uint32_t n = (uint32_t)(wn + (nip * 2 + tsel) * 8 + bn2);
                const uint32_t kb = (uint32_t)(ks * 2 + khalf);
                const uint32_t addr = BhB + n * 128 + ((kb ^ (n & 7)) << 4);
                uint32_t t[4];
                ldsm_x4(t, addr);
                bh[2 * nip][0] = t[0]; bh[2 * nip][1] = t[1];
                bh[2 * nip + 1][0] = t[2]; bh[2 * nip + 1][1] = t[3];
            }
#pragma unroll
            for (int mi = 0; mi < 4; ++mi)
#pragma unroll
                for (int ni = 0; ni < 8; ++ni)
                    mma_f16(acc[mi][ni], ah[mi], bh[ni]);
        }
    };

    loadStage(0, 0); CP_COMMIT();
    loadStage(1, 1); CP_COMMIT();

    for (int c = 0; c < 8; ++c) {
        CP_WAIT(1);
        __syncthreads();
        if (c + 2 < 8) loadStage(c + 2, (c + 2) % 3);
        CP_COMMIT();
        compute(c % 3);
    }

    // epilogue
    {
        const int t2 = (lid & 3) * 2;
        const int gg = lid >> 2;
        float2 bb[8];
#pragma unroll
        for (int ni = 0; ni < 8; ++ni) {
            if (BIAS_MODE == 2 || colBase < 512)
                bb[ni] = *reinterpret_cast<const float2*>(bias + colBase + wn + ni * 8 + t2);
            else
                bb[ni] = make_float2(0.f, 0.f);
        }
#pragma unroll
        for (int mi = 0; mi < 4; ++mi) {
            const int r0 = rowBase + wm + mi * 16 + gg;
#pragma unroll
            for (int ni = 0; ni < 8; ++ni) {
                const int cc = colBase + wn + ni * 8 + t2;
                float2 v0, v1;
                v0.x = acc[mi][ni][0] + bb[ni].x;
                v0.y = acc[mi][ni][1] + bb[ni].y;
                v1.x = acc[mi][ni][2] + bb[ni].x;
                v1.y = acc[mi][ni][3] + bb[ni].y;
                *reinterpret_cast<float2*>(out + (size_t)r0 * outStride + cc) = v0;
                *reinterpret_cast<float2*>(out + (size_t)(r0 + 8) * outStride + cc) = v1;
            }
        }
    }
}

// ---------------------------------------------------------------------------
extern "C" void kernel_launch(void* const* d_in, const int* in_sizes, int n_in,
                              void* d_out, int out_size)
{
    const float* F  = (const float*)d_in[0];   // person_feats (64,32,512)
    const float* W1 = (const float*)d_in[1];   // (512, 1024)
    const float* b1 = (const float*)d_in[2];   // (512,)
    const float* W2 = (const float*)d_in[3];   // (512, 512)
    const float* b2 = (const float*)d_in[4];   // (512,)
    float* out = (float*)d_out;                // (64, 992, 512)

    cudaFuncSetAttribute(k_gemm16<1>, cudaFuncAttributeMaxDynamicSharedMemorySize, SMEM_B3);
    cudaFuncSetAttribute(k_gemm16<2>, cudaFuncAttributeMaxDynamicSharedMemorySize, SMEM_B3);

    unsigned short *Fh, *W1h, *W2h, *Hh;
    float* P;
    cudaGetSymbolAddress((void**)&Fh,  g_Fh);
    cudaGetSymbolAddress((void**)&W1h, g_W1h);
    cudaGetSymbolAddress((void**)&W2h, g_W2h);
    cudaGetSymbolAddress((void**)&Hh,  g_Hh);
    cudaGetSymbolAddress((void**)&P,   g_P);

    // 1) convert all inputs to fp16 in one launch
    k_prep<<<1792, 256>>>(F, W1, W2);

    // 2) P = F @ W1'^T (+ b1 on first 512 cols): M=2048, N=1024
    {
        dim3 g(8, 16);
        k_gemm16<1><<<g, 128, SMEM_B3>>>(Fh, W1h, b1, P, 1024);
    }

    // 3) H = fp16(relu(P1 + P2))
    k_hsplit<<<MROWS / 8, 256>>>();

    // 4) out = Hh @ W2h^T + b2: M=63488, N=512
    {
        dim3 g(4, MROWS / 128);
        k_gemm16<2><<<g, 128, SMEM_B3>>>(Hh, W2h, b2, out, 512);
    }
}

// round 13
// speedup vs baseline: 5.1818x; 1.1061x over previous
#include <cuda_runtime.h>
#include <cuda_fp16.h>
#include <cstdint>

// ---------------------------------------------------------------------------
// Problem constants
#define BDIM   64
#define NDIM   32
#define DDIM   512
#define NPAIR  992                 // 32*31 ordered pairs
#define MROWS  (BDIM * NPAIR)      // 63488 output rows
#define BNROWS (BDIM * NDIM)       // 2048 person rows

// Scratch (device globals; no allocations allowed)
__device__ __align__(16) unsigned short g_P[(size_t)BNROWS * 1024]; // fp16 partials (4 MB)
__device__ __align__(16) unsigned short g_Fh[BNROWS * 512];        // fp16 of F
__device__ __align__(16) unsigned short g_W1h[1024 * 512];         // fp16 W1 rearranged [c][k]
__device__ __align__(16) unsigned short g_W2h[512 * 512];          // fp16 of W2
__device__ __align__(16) unsigned short g_Hh[(size_t)MROWS * 512]; // fp16 of H (65 MB)

// ---------------------------------------------------------------------------
// Helpers
// ---------------------------------------------------------------------------
__device__ __forceinline__ uint32_t smem_u32(const void* p) {
    uint32_t a;
    asm("{ .reg .u64 t; cvta.to.shared.u64 t, %1; cvt.u32.u64 %0, t; }"
        : "=r"(a) : "l"(p));
    return a;
}
__device__ __forceinline__ void ldsm_x4(uint32_t* r, uint32_t addr) {
    asm volatile("ldmatrix.sync.aligned.m8n8.x4.shared.b16 {%0,%1,%2,%3},[%4];"
        : "=r"(r[0]), "=r"(r[1]), "=r"(r[2]), "=r"(r[3]) : "r"(addr));
}
__device__ __forceinline__ void mma_f16(float* d, const uint32_t* a, const uint32_t* b) {
    asm volatile(
        "mma.sync.aligned.m16n8k16.row.col.f32.f16.f16.f32 "
        "{%0,%1,%2,%3},{%4,%5,%6,%7},{%8,%9},{%0,%1,%2,%3};"
        : "+f"(d[0]), "+f"(d[1]), "+f"(d[2]), "+f"(d[3])
        : "r"(a[0]), "r"(a[1]), "r"(a[2]), "r"(a[3]), "r"(b[0]), "r"(b[1]));
}
__device__ __forceinline__ void cp_async16(uint32_t dst, const void* src) {
    asm volatile("cp.async.cg.shared.global [%0], [%1], 16;"
        :: "r"(dst), "l"(__cvta_generic_to_global(src)) : "memory");
}
#define CP_COMMIT() asm volatile("cp.async.commit_group;" ::: "memory")
#define CP_WAIT(n)  asm volatile("cp.async.wait_group %0;" :: "n"(n) : "memory")

__device__ __forceinline__ uint2 f4_to_h4(float4 v) {
    __half2 a = __floats2half2_rn(v.x, v.y);
    __half2 b = __floats2half2_rn(v.z, v.w);
    return make_uint2(*reinterpret_cast<uint32_t*>(&a), *reinterpret_cast<uint32_t*>(&b));
}

// ---------------------------------------------------------------------------
// k_prep: all input conversions in one launch.
// ---------------------------------------------------------------------------
__global__ __launch_bounds__(256)
void k_prep(const float* __restrict__ F, const float* __restrict__ W1,
            const float* __restrict__ W2)
{
    int idx = blockIdx.x * 256 + threadIdx.x;
    if (idx < 262144) {
        float4 v = reinterpret_cast<const float4*>(F)[idx];
        reinterpret_cast<uint2*>(g_Fh)[idx] = f4_to_h4(v);
    } else if (idx < 393216) {
        int i = idx - 262144;
        int L = i * 4;
        int c = L >> 9;
        int k = L & 511;
        float4 v = *reinterpret_cast<const float4*>(
            W1 + (size_t)(c & 511) * 1024 + ((c >> 9) << 9) + k);
        reinterpret_cast<uint2*>(g_W1h)[i] = f4_to_h4(v);
    } else {
        int i = idx - 393216;
        float4 v = reinterpret_cast<const float4*>(W2)[i];
        reinterpret_cast<uint2*>(g_W2h)[i] = f4_to_h4(v);
    }
}

// ---------------------------------------------------------------------------
// H: H[r][k] = fp16(relu(P[b*32+i][k] + P[b*32+j][512+k]))  (P already fp16)
// 8 warps per block, one row per warp, 16 elems per lane.
// ---------------------------------------------------------------------------
__global__ __launch_bounds__(256)
void k_hsplit()
{
    const int r   = blockIdx.x * 8 + (threadIdx.x >> 5);
    const int lid = threadIdx.x & 31;
    const int b = r / NPAIR;
    const int p = r - b * NPAIR;
    const int i = p / 31;
    const int jj = p - i * 31;
    const int j = jj + (jj >= i ? 1 : 0);

    const unsigned short* p1 = g_P + (size_t)(b * NDIM + i) * 1024 + lid * 16;
    const unsigned short* p2 = g_P + (size_t)(b * NDIM + j) * 1024 + 512 + lid * 16;
    unsigned short* hh = g_Hh + (size_t)r * 512 + lid * 16;

    const __half2 zero = __float2half2_rn(0.0f);
#pragma unroll
    for (int g = 0; g < 2; ++g) {                 // 2 groups of 8 halves
        uint4 u = *reinterpret_cast<const uint4*>(p1 + g * 8);
        uint4 v = *reinterpret_cast<const uint4*>(p2 + g * 8);
        uint4 H;
        const uint32_t* up = &u.x;
        const uint32_t* vp = &v.x;
        uint32_t* hp = &H.x;
#pragma unroll
        for (int q = 0; q < 4; ++q) {
            __half2 a = *reinterpret_cast<const __half2*>(&up[q]);
            __half2 c = *reinterpret_cast<const __half2*>(&vp[q]);
            __half2 s = __hmax2(__hadd2(a, c), zero);
            hp[q] = *reinterpret_cast<uint32_t*>(&s);
        }
        *reinterpret_cast<uint4*>(hh + g * 8) = H;
    }
}

// ---------------------------------------------------------------------------
// k_gemm16: single-term fp16 GEMM, fp32 accumulate.
//   out[r, n] = A[r,:] @ B[n,:] + bias
// CTA 128x128, 128 threads = 4 warps in 2(M)x2(N) grid of 64x64 warp tiles.
// K = 8 chunks of 64. 3-stage cp.async; stage 32KB: A 16K | B 16K. 2 CTAs/SM.
// Register double-buffered fragments: ks+1 ldsm issued before ks MMAs.
// BIAS_MODE 1: bias only when colBase < 512 (gemmA). 2: always (gemmB).
// OUT_HALF 1: store fp16 (gemmA -> P). 0: store fp32.
// ---------------------------------------------------------------------------
#define STG_B    32768
#define SMEM_B3  (3 * STG_B + 1024)

template<int BIAS_MODE, int OUT_HALF>
__global__ __launch_bounds__(128, 2)
void k_gemm16(const unsigned short* __restrict__ A_g,
              const unsigned short* __restrict__ B_g,
              const float* __restrict__ bias,
              void* __restrict__ out_v, int outStride)
{
    extern __shared__ char dsm[];
    const int tid = threadIdx.x;
    const int wid = tid >> 5;
    const int lid = tid & 31;

    uint32_t raw = smem_u32(dsm);
    const uint32_t dbase = (raw + 1023u) & ~1023u;

    const int rowBase = blockIdx.y * 128;
    const int colBase = blockIdx.x * 128;

    const unsigned short* Asrc = A_g + (size_t)rowBase * 512;
    const unsigned short* Bsrc = B_g + (size_t)colBase * 512;

    auto ldt = [&](uint32_t dst, const unsigned short* src, int c) {
#pragma unroll
        for (int g = 0; g < 8; ++g) {
            const int q = tid + 128 * g;
            const int row = q >> 3;
            const int kb  = q & 7;
            const uint32_t off = (uint32_t)row * 128 + (uint32_t)((kb ^ (row & 7)) << 4);
            cp_async16(dst + off, src + (size_t)row * 512 + c * 64 + kb * 8);
        }
    };
    auto loadStage = [&](int c, int s) {
        const uint32_t st = dbase + s * STG_B;
        ldt(st,         Asrc, c);
        ldt(st + 16384, Bsrc, c);
    };

    const int wm = (wid & 1) * 64;
    const int wn = (wid >> 1) * 64;

    float acc[4][8][4];
#pragma unroll
    for (int mi = 0; mi < 4; ++mi)
#pragma unroll
        for (int ni = 0; ni < 8; ++ni)
#pragma unroll
            for (int q = 0; q < 4; ++q) acc[mi][ni][q] = 0.0f;

    const int mrow  = lid & 15;
    const int ksel  = lid >> 4;
    const int bn2   = lid & 7;
    const int khalf = (lid >> 3) & 1;
    const int tsel  = (lid >> 4) & 1;

    // fragment double buffers
    uint32_t ah[2][4][4], bh[2][8][2];

    auto loadFrags = [&](int ks, int buf, uint32_t AhB, uint32_t BhB) {
#pragma unroll
        for (int mi = 0; mi < 4; ++mi) {
            const uint32_t r = (uint32_t)(wm + mi * 16 + mrow);
            const uint32_t kb = (uint32_t)(ks * 2 + ksel);
            const uint32_t addr = AhB + r * 128 + ((kb ^ (r & 7)) << 4);
            ldsm_x4(ah[buf][mi], addr);
        }
#pragma unroll
        for (int nip = 0; nip < 4; ++nip) {
            const uint32_t n = (uint32_t)(wn + (nip * 2 + tsel) * 8 + bn2);
            const uint32_t kb = (uint32_t)(ks * 2 + khalf);
            const uint32_t addr = BhB + n * 128 + ((kb ^ (n & 7)) << 4);
            uint32_t t[4];
            ldsm_x4(t, addr);
            bh[buf][2 * nip][0] = t[0]; bh[buf][2 * nip][1] = t[1];
            bh[buf][2 * nip + 1][0] = t[2]; bh[buf][2 * nip + 1][1] = t[3];
        }
    };

    auto compute = [&](int s) {
        const uint32_t AhB = dbase + s * STG_B;
        const uint32_t BhB = AhB + 16384;
        loadFrags(0, 0, AhB, BhB);
#pragma unroll
        for (int ks = 0; ks < 4; ++ks) {
            const int cur = ks & 1;
            if (ks < 3) loadFrags(ks + 1, cur ^ 1, AhB, BhB);
#pragma unroll
            for (int mi = 0; mi < 4; ++mi)
#pragma unroll
                for (int ni = 0; ni < 8; ++ni)
                    mma_f16(acc[mi][ni], ah[cur][mi], bh[cur][ni]);
        }
    };

    loadStage(0, 0); CP_COMMIT();
    loadStage(1, 1); CP_COMMIT();

    for (int c = 0; c < 8; ++c) {
        CP_WAIT(1);
        __syncthreads();
        if (c + 2 < 8) loadStage(c + 2, (c + 2) % 3);
        CP_COMMIT();
        compute(c % 3);
    }

    // epilogue
    {
        const int t2 = (lid & 3) * 2;
        const int gg = lid >> 2;
        float2 bb[8];
#pragma unroll
        for (int ni = 0; ni < 8; ++ni) {
            if (BIAS_MODE == 2 || colBase < 512)
                bb[ni] = *reinterpret_cast<const float2*>(bias + colBase + wn + ni * 8 + t2);
            else
                bb[ni] = make_float2(0.f, 0.f);
        }
#pragma unroll
        for (int mi = 0; mi < 4; ++mi) {
            const int r0 = rowBase + wm + mi * 16 + gg;
#pragma unroll
            for (int ni = 0; ni < 8; ++ni) {
                const int cc = colBase + wn + ni * 8 + t2;
                float2 v0, v1;
                v0.x = acc[mi][ni][0] + bb[ni].x;
                v0.y = acc[mi][ni][1] + bb[ni].y;
                v1.x = acc[mi][ni][2] + bb[ni].x;
                v1.y = acc[mi][ni][3] + bb[ni].y;
                if (OUT_HALF) {
                    unsigned short* o16 = (unsigned short*)out_v;
                    __half2 h0 = __floats2half2_rn(v0.x, v0.y);
                    __half2 h1 = __floats2half2_rn(v1.x, v1.y);
                    *reinterpret_cast<uint32_t*>(o16 + (size_t)r0 * outStride + cc) =
                        *reinterpret_cast<uint32_t*>(&h0);
                    *reinterpret_cast<uint32_t*>(o16 + (size_t)(r0 + 8) * outStride + cc) =
                        *reinterpret_cast<uint32_t*>(&h1);
                } else {
                    float* o32 = (float*)out_v;
                    *reinterpret_cast<float2*>(o32 + (size_t)r0 * outStride + cc) = v0;
                    *reinterpret_cast<float2*>(o32 + (size_t)(r0 + 8) * outStride + cc) = v1;
                }
            }
        }
    }
}

// ---------------------------------------------------------------------------
extern "C" void kernel_launch(void* const* d_in, const int* in_sizes, int n_in,
                              void* d_out, int out_size)
{
    const float* F  = (const float*)d_in[0];   // person_feats (64,32,512)
    const float* W1 = (const float*)d_in[1];   // (512, 1024)
    const float* b1 = (const float*)d_in[2];   // (512,)
    const float* W2 = (const float*)d_in[3];   // (512, 512)
    const float* b2 = (const float*)d_in[4];   // (512,)
    float* out = (float*)d_out;                // (64, 992, 512)

    cudaFuncSetAttribute(k_gemm16<1,1>, cudaFuncAttributeMaxDynamicSharedMemorySize, SMEM_B3);
    cudaFuncSetAttribute(k_gemm16<2,0>, cudaFuncAttributeMaxDynamicSharedMemorySize, SMEM_B3);

    unsigned short *Fh, *W1h, *W2h, *Hh, *Ph;
    cudaGetSymbolAddress((void**)&Fh,  g_Fh);
    cudaGetSymbolAddress((void**)&W1h, g_W1h);
    cudaGetSymbolAddress((void**)&W2h, g_W2h);
    cudaGetSymbolAddress((void**)&Hh,  g_Hh);
    cudaGetSymbolAddress((void**)&Ph,  g_P);

    // 1) convert all inputs to fp16 in one launch
    k_prep<<<1792, 256>>>(F, W1, W2);

    // 2) P = F @ W1'^T (+ b1 on first 512 cols) -> fp16: M=2048, N=1024
    {
        dim3 g(8, 16);
        k_gemm16<1,1><<<g, 128, SMEM_B3>>>(Fh, W1h, b1, Ph, 1024);
    }

    // 3) H = fp16(relu(P1 + P2))
    k_hsplit<<<MROWS / 8, 256>>>();

    // 4) out = Hh @ W2h^T + b2: M=63488, N=512
    {
        dim3 g(4, MROWS / 128);
        k_gemm16<2,0><<<g, 128, SMEM_B3>>>(Hh, W2h, b2, out, 512);
    }
}